// round 6
// baseline (speedup 1.0000x reference)
#include <cuda_runtime.h>
#include <math.h>

#define B_    2
#define S_    2048
#define D_    768
#define H_    12
#define DEP_  64
#define BH_   (B_*H_)            // 24
#define MROWS (B_*S_)            // 4096
#define OUT_ELEMS (B_*S_*D_)     // 3145728
#define ATTN_ELEMS (BH_*S_*S_)   // 100663296

// ---- scratch (alloc-free, __device__ globals) ----
__device__ float g_Qp[BH_*S_*DEP_];
__device__ float g_Kp[BH_*S_*DEP_];
__device__ float g_Vp[BH_*S_*DEP_];
__device__ float g_ctx[MROWS*D_];
__device__ float g_rowmax[BH_*S_];
__device__ float g_rowinv[BH_*S_];
__device__ float g_attn_scratch[ATTN_ELEMS];  // used only if d_out lacks attn

__device__ __forceinline__ float neg_inf() { return __int_as_float(0xff800000); }

// ---- tf32 helpers ----
__device__ __forceinline__ unsigned f2tf(float x) {
    unsigned r;
    asm("cvt.rna.tf32.f32 %0, %1;" : "=r"(r) : "f"(x));
    return r;
}
__device__ __forceinline__ void split_tf(float x, unsigned& h, unsigned& l) {
    h = f2tf(x);
    l = f2tf(x - __uint_as_float(h));
}
// D += A(16x8) * B(8x8), tf32 operands, f32 accumulate
__device__ __forceinline__ void mma8(float* c,
                                     unsigned a0, unsigned a1, unsigned a2, unsigned a3,
                                     unsigned b0, unsigned b1) {
    asm volatile(
        "mma.sync.aligned.m16n8k8.row.col.f32.tf32.tf32.f32 "
        "{%0,%1,%2,%3}, {%4,%5,%6,%7}, {%8,%9}, {%0,%1,%2,%3};\n"
        : "+f"(c[0]), "+f"(c[1]), "+f"(c[2]), "+f"(c[3])
        : "r"(a0), "r"(a1), "r"(a2), "r"(a3), "r"(b0), "r"(b1));
}

// ======================================================================
// C[M,N] = alpha * (X[M,K] @ W[N,K]^T + bias[N])   via 3xTF32 mma
// block tile 128(m) x 64(n), BK=16, 256 threads.
// Warp layout: 4(m) x 2(n); each warp 32x32 (mt=2 x nt=4 m16n8 tiles).
// head_split: write [B,H,S,DEP] layout (n-tile == one head).
// ======================================================================
__global__ __launch_bounds__(256)
void gemm_xwT_mma(const float* __restrict__ X,
                  const float* __restrict__ W,
                  const float* __restrict__ bias,
                  float* __restrict__ C,
                  int K, int N, float alpha, int head_split)
{
    __shared__ unsigned Ah[128][20], Al[128][20];
    __shared__ unsigned Bh[64][20],  Bl[64][20];

    const int t = threadIdx.x, wid = t >> 5, lane = t & 31;
    const int gid = lane >> 2, tig = lane & 3;
    const int n0 = blockIdx.x * 64, m0 = blockIdx.y * 128;
    const int wm = (wid & 3) * 32, wn = (wid >> 2) * 32;

    const int lr = t >> 2;        // 0..63
    const int lkg = t & 3;        // k-group (float4)

    const float* Xp0 = X + (size_t)(m0 + lr) * K + lkg * 4;
    const float* Xp1 = Xp0 + (size_t)64 * K;
    const float* Wp  = W + (size_t)(n0 + lr) * K + lkg * 4;

    float acc[2][4][4];
#pragma unroll
    for (int i = 0; i < 2; i++)
#pragma unroll
        for (int j = 0; j < 4; j++)
#pragma unroll
            for (int q = 0; q < 4; q++) acc[i][j][q] = 0.0f;

    float4 xv0 = *(const float4*)Xp0;
    float4 xv1 = *(const float4*)Xp1;
    float4 wv  = *(const float4*)Wp;

    for (int k0 = 0; k0 < K; k0 += 16) {
        {
            const float x0[4] = {xv0.x, xv0.y, xv0.z, xv0.w};
            const float x1[4] = {xv1.x, xv1.y, xv1.z, xv1.w};
            const float w4[4] = {wv.x,  wv.y,  wv.z,  wv.w};
#pragma unroll
            for (int j = 0; j < 4; j++) {
                unsigned h, l;
                split_tf(x0[j], h, l); Ah[lr][lkg*4+j] = h;      Al[lr][lkg*4+j] = l;
                split_tf(x1[j], h, l); Ah[64+lr][lkg*4+j] = h;   Al[64+lr][lkg*4+j] = l;
                split_tf(w4[j], h, l); Bh[lr][lkg*4+j] = h;      Bl[lr][lkg*4+j] = l;
            }
        }
        __syncthreads();

        if (k0 + 16 < K) {
            xv0 = *(const float4*)(Xp0 + k0 + 16);
            xv1 = *(const float4*)(Xp1 + k0 + 16);
            wv  = *(const float4*)(Wp  + k0 + 16);
        }

#pragma unroll
        for (int kk = 0; kk < 16; kk += 8) {
            unsigned ah[2][4], al[2][4];
#pragma unroll
            for (int mt = 0; mt < 2; mt++) {
                const int r = wm + mt * 16 + gid;
                ah[mt][0] = Ah[r][kk+tig];     ah[mt][1] = Ah[r+8][kk+tig];
                ah[mt][2] = Ah[r][kk+tig+4];   ah[mt][3] = Ah[r+8][kk+tig+4];
                al[mt][0] = Al[r][kk+tig];     al[mt][1] = Al[r+8][kk+tig];
                al[mt][2] = Al[r][kk+tig+4];   al[mt][3] = Al[r+8][kk+tig+4];
            }
#pragma unroll
            for (int nt = 0; nt < 4; nt++) {
                const int cn = wn + nt * 8 + gid;
                const unsigned bh0 = Bh[cn][kk+tig], bh1 = Bh[cn][kk+tig+4];
                const unsigned bl0 = Bl[cn][kk+tig], bl1 = Bl[cn][kk+tig+4];
#pragma unroll
                for (int mt = 0; mt < 2; mt++) {
                    mma8(acc[mt][nt], ah[mt][0],ah[mt][1],ah[mt][2],ah[mt][3], bh0, bh1);
                    mma8(acc[mt][nt], ah[mt][0],ah[mt][1],ah[mt][2],ah[mt][3], bl0, bl1);
                    mma8(acc[mt][nt], al[mt][0],al[mt][1],al[mt][2],al[mt][3], bh0, bh1);
                }
            }
        }
        __syncthreads();
    }

    // epilogue
#pragma unroll
    for (int mt = 0; mt < 2; mt++) {
#pragma unroll
        for (int nt = 0; nt < 4; nt++) {
            const int r0 = m0 + wm + mt*16 + gid;
            const int r1 = r0 + 8;
            const int c  = n0 + wn + nt*8 + tig*2;
            const float b0v = bias[c], b1v = bias[c+1];
            float2 v0, v1;
            v0.x = alpha * (acc[mt][nt][0] + b0v);
            v0.y = alpha * (acc[mt][nt][1] + b1v);
            v1.x = alpha * (acc[mt][nt][2] + b0v);
            v1.y = alpha * (acc[mt][nt][3] + b1v);
            if (head_split) {
                const int h = n0 / DEP_;
                const int dd = c - n0;
                const int b0_ = r0 / S_, s0 = r0 % S_;
                const int b1_ = r1 / S_, s1 = r1 % S_;
                *(float2*)(C + (((size_t)(b0_*H_ + h))*S_ + s0)*DEP_ + dd) = v0;
                *(float2*)(C + (((size_t)(b1_*H_ + h))*S_ + s1)*DEP_ + dd) = v1;
            } else {
                *(float2*)(C + (size_t)r0 * N + c) = v0;
                *(float2*)(C + (size_t)r1 * N + c) = v1;
            }
        }
    }
}

// ======================================================================
// logits[bh,m,n] = sum_k Qp[bh,m,k]*Kp[bh,n,k]   (Q pre-scaled by 1/8)
// masked -inf where mask[b,n]==0.  128x128 tile, 3xTF32 mma.
// Warp layout 2(m) x 4(n); warp 64x32 (mt=4 x nt=4 tiles). grid (16,16,24)
// ======================================================================
__global__ __launch_bounds__(256)
void logits_mma(const float* __restrict__ Qp,
                const float* __restrict__ Kp,
                const int*   __restrict__ mask,
                float* __restrict__ attn)
{
    __shared__ unsigned Ah[128][20], Al[128][20];
    __shared__ unsigned Bh[128][20], Bl[128][20];
    __shared__ int smask[128];

    const int t = threadIdx.x, wid = t >> 5, lane = t & 31;
    const int gid = lane >> 2, tig = lane & 3;
    const int n0 = blockIdx.x * 128, m0 = blockIdx.y * 128;
    const int bh = blockIdx.z, b = bh / H_;
    const int wm = (wid & 1) * 64, wn = (wid >> 1) * 32;

    if (t < 128) smask[t] = mask[b * S_ + n0 + t];

    const int lr = t >> 2, lkg = t & 3;
    const float* Qb = Qp + ((size_t)bh * S_ + m0) * DEP_;
    const float* Kb = Kp + ((size_t)bh * S_ + n0) * DEP_;
    const float* Qp0 = Qb + (size_t)lr * DEP_ + lkg * 4;
    const float* Qp1 = Qp0 + (size_t)64 * DEP_;
    const float* Kp0 = Kb + (size_t)lr * DEP_ + lkg * 4;
    const float* Kp1 = Kp0 + (size_t)64 * DEP_;

    float acc[4][4][4];
#pragma unroll
    for (int i = 0; i < 4; i++)
#pragma unroll
        for (int j = 0; j < 4; j++)
#pragma unroll
            for (int q = 0; q < 4; q++) acc[i][j][q] = 0.0f;

    float4 q0 = *(const float4*)Qp0;
    float4 q1 = *(const float4*)Qp1;
    float4 k0v = *(const float4*)Kp0;
    float4 k1v = *(const float4*)Kp1;

    for (int k0 = 0; k0 < DEP_; k0 += 16) {
        {
            const float a0[4] = {q0.x,q0.y,q0.z,q0.w};
            const float a1[4] = {q1.x,q1.y,q1.z,q1.w};
            const float c0[4] = {k0v.x,k0v.y,k0v.z,k0v.w};
            const float c1[4] = {k1v.x,k1v.y,k1v.z,k1v.w};
#pragma unroll
            for (int j = 0; j < 4; j++) {
                unsigned h, l;
                split_tf(a0[j], h, l); Ah[lr][lkg*4+j] = h;    Al[lr][lkg*4+j] = l;
                split_tf(a1[j], h, l); Ah[64+lr][lkg*4+j] = h; Al[64+lr][lkg*4+j] = l;
                split_tf(c0[j], h, l); Bh[lr][lkg*4+j] = h;    Bl[lr][lkg*4+j] = l;
                split_tf(c1[j], h, l); Bh[64+lr][lkg*4+j] = h; Bl[64+lr][lkg*4+j] = l;
            }
        }
        __syncthreads();

        if (k0 + 16 < DEP_) {
            q0  = *(const float4*)(Qp0 + k0 + 16);
            q1  = *(const float4*)(Qp1 + k0 + 16);
            k0v = *(const float4*)(Kp0 + k0 + 16);
            k1v = *(const float4*)(Kp1 + k0 + 16);
        }

#pragma unroll
        for (int kk = 0; kk < 16; kk += 8) {
            unsigned ah[4][4], al[4][4];
#pragma unroll
            for (int mt = 0; mt < 4; mt++) {
                const int r = wm + mt * 16 + gid;
                ah[mt][0] = Ah[r][kk+tig];     ah[mt][1] = Ah[r+8][kk+tig];
                ah[mt][2] = Ah[r][kk+tig+4];   ah[mt][3] = Ah[r+8][kk+tig+4];
                al[mt][0] = Al[r][kk+tig];     al[mt][1] = Al[r+8][kk+tig];
                al[mt][2] = Al[r][kk+tig+4];   al[mt][3] = Al[r+8][kk+tig+4];
            }
#pragma unroll
            for (int nt = 0; nt < 4; nt++) {
                const int cn = wn + nt * 8 + gid;
                const unsigned bh0 = Bh[cn][kk+tig], bh1 = Bh[cn][kk+tig+4];
                const unsigned bl0 = Bl[cn][kk+tig], bl1 = Bl[cn][kk+tig+4];
#pragma unroll
                for (int mt = 0; mt < 4; mt++) {
                    mma8(acc[mt][nt], ah[mt][0],ah[mt][1],ah[mt][2],ah[mt][3], bh0, bh1);
                    mma8(acc[mt][nt], ah[mt][0],ah[mt][1],ah[mt][2],ah[mt][3], bl0, bl1);
                    mma8(acc[mt][nt], al[mt][0],al[mt][1],al[mt][2],al[mt][3], bh0, bh1);
                }
            }
        }
        __syncthreads();
    }

    float* Cb = attn + (size_t)bh * S_ * S_;
#pragma unroll
    for (int mt = 0; mt < 4; mt++) {
#pragma unroll
        for (int nt = 0; nt < 4; nt++) {
            const int r0 = m0 + wm + mt*16 + gid;
            const int r1 = r0 + 8;
            const int lc = wn + nt*8 + tig*2;        // local col 0..127
            const int c  = n0 + lc;
            const bool z0 = (smask[lc] == 0), z1 = (smask[lc+1] == 0);
            float2 v0, v1;
            v0.x = z0 ? neg_inf() : acc[mt][nt][0];
            v0.y = z1 ? neg_inf() : acc[mt][nt][1];
            v1.x = z0 ? neg_inf() : acc[mt][nt][2];
            v1.y = z1 ? neg_inf() : acc[mt][nt][3];
            *(float2*)(Cb + (size_t)r0 * S_ + c) = v0;
            *(float2*)(Cb + (size_t)r1 * S_ + c) = v1;
        }
    }
}

// ======================================================================
// Row stats over raw logits: gmax[row], ginv[row] = 1/sum(exp(x-max))
// ======================================================================
__global__ __launch_bounds__(256)
void row_stats_kernel(const float* __restrict__ attn,
                      float* __restrict__ gmax,
                      float* __restrict__ ginv)
{
    const float* p = attn + (size_t)blockIdx.x * S_;
    const int t = threadIdx.x;

    float x[8];
    float mx = neg_inf();
#pragma unroll
    for (int i = 0; i < 8; i++) { x[i] = p[t + i*256]; mx = fmaxf(mx, x[i]); }

    __shared__ float redm[8];
    __shared__ float reds[8];

#pragma unroll
    for (int o = 16; o > 0; o >>= 1)
        mx = fmaxf(mx, __shfl_xor_sync(0xffffffffu, mx, o));
    if ((t & 31) == 0) redm[t >> 5] = mx;
    __syncthreads();
    float bm = redm[0];
#pragma unroll
    for (int i = 1; i < 8; i++) bm = fmaxf(bm, redm[i]);

    float s = 0.0f;
#pragma unroll
    for (int i = 0; i < 8; i++) s += __expf(x[i] - bm);
#pragma unroll
    for (int o = 16; o > 0; o >>= 1)
        s += __shfl_xor_sync(0xffffffffu, s, o);
    if ((t & 31) == 0) reds[t >> 5] = s;
    __syncthreads();

    if (t == 0) {
        float tot = 0.0f;
#pragma unroll
        for (int i = 0; i < 8; i++) tot += reds[i];
        gmax[blockIdx.x] = bm;
        ginv[blockIdx.x] = 1.0f / tot;
    }
}

// ======================================================================
// ctx = softmax(logits) @ V via 3xTF32 mma, normalizing attn in place.
// Block: 128(m) x 64(d), n-slabs of 16. Warp layout 4(m) x 2(d);
// warp 32x32 (mt=2 x dt=4). grid (16,24)
// ======================================================================
__global__ __launch_bounds__(256)
void ctx_mma(float* __restrict__ attn,
             const float* __restrict__ Vp,
             const float* __restrict__ gmax,
             const float* __restrict__ ginv,
             float* __restrict__ ctx)
{
    __shared__ unsigned Ah[128][20], Al[128][20];
    __shared__ unsigned Vh[16][72],  Vl[16][72];
    __shared__ float smax[128], sinv[128];

    const int t = threadIdx.x, wid = t >> 5, lane = t & 31;
    const int gid = lane >> 2, tig = lane & 3;
    const int m0 = blockIdx.x * 128;
    const int bh = blockIdx.y;
    const int b  = bh / H_, h = bh % H_;
    const int wm = (wid & 3) * 32, wd = (wid >> 2) * 32;

    if (t < 128) {
        smax[t] = gmax[bh * S_ + m0 + t];
        sinv[t] = ginv[bh * S_ + m0 + t];
    }
    __syncthreads();

    const int lr = t >> 2, lng = t & 3;        // A loader: row 0..63(+64), n-group
    const int vr = t >> 4, vdg = t & 15;       // V loader: slab row 0..15, d-group

    float* Ap0 = attn + ((size_t)bh * S_ + m0 + lr) * S_ + lng * 4;
    float* Ap1 = Ap0 + (size_t)64 * S_;
    const float* Vpp = Vp + ((size_t)bh * S_ + vr) * DEP_ + vdg * 4;

    const float mr0 = smax[lr],    ir0 = sinv[lr];
    const float mr1 = smax[64+lr], ir1 = sinv[64+lr];

    float acc[2][4][4];
#pragma unroll
    for (int i = 0; i < 2; i++)
#pragma unroll
        for (int j = 0; j < 4; j++)
#pragma unroll
            for (int q = 0; q < 4; q++) acc[i][j][q] = 0.0f;

    float4 a0v = *(const float4*)Ap0;
    float4 a1v = *(const float4*)Ap1;
    float4 vv  = *(const float4*)Vpp;

    for (int nc = 0; nc < S_; nc += 16) {
        {
            float4 p0, p1;
            p0.x = __expf(a0v.x - mr0) * ir0;  p0.y = __expf(a0v.y - mr0) * ir0;
            p0.z = __expf(a0v.z - mr0) * ir0;  p0.w = __expf(a0v.w - mr0) * ir0;
            p1.x = __expf(a1v.x - mr1) * ir1;  p1.y = __expf(a1v.y - mr1) * ir1;
            p1.z = __expf(a1v.z - mr1) * ir1;  p1.w = __expf(a1v.w - mr1) * ir1;
            *(float4*)(Ap0 + nc) = p0;         // final normalized attn
            *(float4*)(Ap1 + nc) = p1;
            const float q0[4] = {p0.x,p0.y,p0.z,p0.w};
            const float q1[4] = {p1.x,p1.y,p1.z,p1.w};
            const float w4[4] = {vv.x,vv.y,vv.z,vv.w};
#pragma unroll
            for (int j = 0; j < 4; j++) {
                unsigned hh, ll;
                split_tf(q0[j], hh, ll); Ah[lr][lng*4+j] = hh;    Al[lr][lng*4+j] = ll;
                split_tf(q1[j], hh, ll); Ah[64+lr][lng*4+j] = hh; Al[64+lr][lng*4+j] = ll;
                split_tf(w4[j], hh, ll); Vh[vr][vdg*4+j] = hh;    Vl[vr][vdg*4+j] = ll;
            }
        }
        __syncthreads();

        if (nc + 16 < S_) {
            a0v = *(const float4*)(Ap0 + nc + 16);
            a1v = *(const float4*)(Ap1 + nc + 16);
            vv  = *(const float4*)(Vpp + (size_t)(nc + 16) * DEP_);
        }

#pragma unroll
        for (int kk = 0; kk < 16; kk += 8) {
            unsigned ah[2][4], al[2][4];
#pragma unroll
            for (int mt = 0; mt < 2; mt++) {
                const int r = wm + mt * 16 + gid;
                ah[mt][0] = Ah[r][kk+tig];     ah[mt][1] = Ah[r+8][kk+tig];
                ah[mt][2] = Ah[r][kk+tig+4];   ah[mt][3] = Ah[r+8][kk+tig+4];
                al[mt][0] = Al[r][kk+tig];     al[mt][1] = Al[r+8][kk+tig];
                al[mt][2] = Al[r][kk+tig+4];   al[mt][3] = Al[r+8][kk+tig+4];
            }
#pragma unroll
            for (int dt = 0; dt < 4; dt++) {
                const int cd = wd + dt * 8 + gid;
                const unsigned bh0 = Vh[kk+tig][cd],   bh1 = Vh[kk+tig+4][cd];
                const unsigned bl0 = Vl[kk+tig][cd],   bl1 = Vl[kk+tig+4][cd];
#pragma unroll
                for (int mt = 0; mt < 2; mt++) {
                    mma8(acc[mt][dt], ah[mt][0],ah[mt][1],ah[mt][2],ah[mt][3], bh0, bh1);
                    mma8(acc[mt][dt], ah[mt][0],ah[mt][1],ah[mt][2],ah[mt][3], bl0, bl1);
                    mma8(acc[mt][dt], al[mt][0],al[mt][1],al[mt][2],al[mt][3], bh0, bh1);
                }
            }
        }
        __syncthreads();
    }

#pragma unroll
    for (int mt = 0; mt < 2; mt++) {
#pragma unroll
        for (int dt = 0; dt < 4; dt++) {
            const int r0 = m0 + wm + mt*16 + gid;
            const int r1 = r0 + 8;
            const int d  = wd + dt*8 + tig*2;
            float2 v0 = {acc[mt][dt][0], acc[mt][dt][1]};
            float2 v1 = {acc[mt][dt][2], acc[mt][dt][3]};
            *(float2*)(ctx + ((size_t)b * S_ + r0) * D_ + h * DEP_ + d) = v0;
            *(float2*)(ctx + ((size_t)b * S_ + r1) * D_ + h * DEP_ + d) = v1;
        }
    }
}

// ======================================================================
extern "C" void kernel_launch(void* const* d_in, const int* in_sizes, int n_in,
                              void* d_out, int out_size)
{
    const float* q    = (const float*)d_in[0];
    const float* k    = (const float*)d_in[1];
    const float* v    = (const float*)d_in[2];
    const int*   mask = (const int*)  d_in[3];
    const float* wq_w = (const float*)d_in[4];
    const float* wq_b = (const float*)d_in[5];
    const float* wk_w = (const float*)d_in[6];
    const float* wk_b = (const float*)d_in[7];
    const float* wv_w = (const float*)d_in[8];
    const float* wv_b = (const float*)d_in[9];
    const float* wo_w = (const float*)d_in[10];
    const float* wo_b = (const float*)d_in[11];
    float* out = (float*)d_out;

    float *Qp, *Kp, *Vp, *ctxp, *rmax, *rinv, *attn_s;
    cudaGetSymbolAddress((void**)&Qp,     g_Qp);
    cudaGetSymbolAddress((void**)&Kp,     g_Kp);
    cudaGetSymbolAddress((void**)&Vp,     g_Vp);
    cudaGetSymbolAddress((void**)&ctxp,   g_ctx);
    cudaGetSymbolAddress((void**)&rmax,   g_rowmax);
    cudaGetSymbolAddress((void**)&rinv,   g_rowinv);
    cudaGetSymbolAddress((void**)&attn_s, g_attn_scratch);

    const long long need = (long long)OUT_ELEMS + (long long)ATTN_ELEMS;
    float* attn = ((long long)out_size >= need) ? (out + OUT_ELEMS) : attn_s;

    // Q/K/V projections (Q pre-scaled by 1/sqrt(64) = 0.125)
    dim3 pgrid(D_/64, MROWS/128);
    gemm_xwT_mma<<<pgrid, 256>>>(q, wq_w, wq_b, Qp, D_, D_, 0.125f, 1);
    gemm_xwT_mma<<<pgrid, 256>>>(k, wk_w, wk_b, Kp, D_, D_, 1.0f, 1);
    gemm_xwT_mma<<<pgrid, 256>>>(v, wv_w, wv_b, Vp, D_, D_, 1.0f, 1);

    // raw masked logits
    logits_mma<<<dim3(S_/128, S_/128, BH_), 256>>>(Qp, Kp, mask, attn);

    // per-row softmax stats
    row_stats_kernel<<<dim3(BH_ * S_), 256>>>(attn, rmax, rinv);

    // ctx = softmax @ V; normalizes attn in place as it goes
    ctx_mma<<<dim3(S_/128, BH_), 256>>>(attn, Vp, rmax, rinv, ctxp);

    // output projection
    gemm_xwT_mma<<<pgrid, 256>>>(ctxp, wo_w, wo_b, out, D_, D_, 1.0f, 0);
}

// round 7
// speedup vs baseline: 2.1137x; 2.1137x over previous
#include <cuda_runtime.h>
#include <cuda_bf16.h>
#include <math.h>

#define B_    2
#define S_    2048
#define D_    768
#define H_    12
#define DEP_  64
#define BH_   (B_*H_)            // 24
#define MROWS (B_*S_)            // 4096
#define OUT_ELEMS (B_*S_*D_)     // 3145728
#define ATTN_ELEMS (BH_*S_*S_)   // 100663296

// ---- scratch (alloc-free, __device__ globals) ----
__device__ float g_Qp[BH_*S_*DEP_];
__device__ float g_Kp[BH_*S_*DEP_];
__device__ float g_Vp[BH_*S_*DEP_];
__device__ float g_ctx[MROWS*D_];
__device__ float g_rowmax[BH_*S_];
__device__ float g_rowinv[BH_*S_];
__device__ float g_attn_scratch[ATTN_ELEMS];

__device__ __forceinline__ float neg_inf() { return __int_as_float(0xff800000); }

// ---- bf16 split helpers ----
// x = hi + lo with hi, lo bf16; residual ~2^-17 * |x|
__device__ __forceinline__ void split2(float x, float y, unsigned& h, unsigned& l) {
    __nv_bfloat162 hv = __floats2bfloat162_rn(x, y);
    float2 hf = __bfloat1622float2(hv);
    __nv_bfloat162 lv = __floats2bfloat162_rn(x - hf.x, y - hf.y);
    h = *(unsigned*)&hv;
    l = *(unsigned*)&lv;
}

// D += A(16x16) * B(16x8), bf16 in, f32 accumulate
__device__ __forceinline__ void mma16(float* c,
                                      unsigned a0, unsigned a1, unsigned a2, unsigned a3,
                                      unsigned b0, unsigned b1) {
    asm volatile(
        "mma.sync.aligned.m16n8k16.row.col.f32.bf16.bf16.f32 "
        "{%0,%1,%2,%3}, {%4,%5,%6,%7}, {%8,%9}, {%0,%1,%2,%3};\n"
        : "+f"(c[0]), "+f"(c[1]), "+f"(c[2]), "+f"(c[3])
        : "r"(a0), "r"(a1), "r"(a2), "r"(a3), "r"(b0), "r"(b1));
}

// ======================================================================
// C[M,N] = alpha * (X[M,K] @ W[N,K]^T + bias[N])  via 3-product bf16 mma
// block tile 128(m) x 64(n), BK=32, 256 threads, warps 4(m) x 2(n),
// warp tile 32x32 (mt=2 x nt=4). head_split: write [B,H,S,DEP].
// ======================================================================
__global__ __launch_bounds__(256, 2)
void gemm_xwT_bf16(const float* __restrict__ X,
                   const float* __restrict__ W,
                   const float* __restrict__ bias,
                   float* __restrict__ C,
                   int K, int N, float alpha, int head_split)
{
    __shared__ unsigned Ah[128][20], Al[128][20];  // 16 k-pairs + pad
    __shared__ unsigned Bh[64][20],  Bl[64][20];

    const int t = threadIdx.x, wid = t >> 5, lane = t & 31;
    const int gid = lane >> 2, tig = lane & 3;
    const int n0 = blockIdx.x * 64, m0 = blockIdx.y * 128;
    const int wm = (wid & 3) * 32, wn = (wid >> 2) * 32;

    const int lr = t >> 1, lg = t & 1;   // A: row 0..127, half-row (16 floats)
    const int br = t >> 2, bg = t & 3;   // B: row 0..63, quarter-row (8 floats)

    const float* Xp = X + (size_t)(m0 + lr) * K + lg * 16;
    const float* Wp = W + (size_t)(n0 + br) * K + bg * 8;

    float acc[2][4][4];
#pragma unroll
    for (int i = 0; i < 2; i++)
#pragma unroll
        for (int j = 0; j < 4; j++)
#pragma unroll
            for (int q = 0; q < 4; q++) acc[i][j][q] = 0.0f;

    float4 xa[4], wb[2];
#pragma unroll
    for (int j = 0; j < 4; j++) xa[j] = *(const float4*)(Xp + j * 4);
#pragma unroll
    for (int j = 0; j < 2; j++) wb[j] = *(const float4*)(Wp + j * 4);

    for (int k0 = 0; k0 < K; k0 += 32) {
#pragma unroll
        for (int j = 0; j < 4; j++) {
            unsigned h, l;
            split2(xa[j].x, xa[j].y, h, l);
            Ah[lr][lg*8 + 2*j]     = h;  Al[lr][lg*8 + 2*j]     = l;
            split2(xa[j].z, xa[j].w, h, l);
            Ah[lr][lg*8 + 2*j + 1] = h;  Al[lr][lg*8 + 2*j + 1] = l;
        }
#pragma unroll
        for (int j = 0; j < 2; j++) {
            unsigned h, l;
            split2(wb[j].x, wb[j].y, h, l);
            Bh[br][bg*4 + 2*j]     = h;  Bl[br][bg*4 + 2*j]     = l;
            split2(wb[j].z, wb[j].w, h, l);
            Bh[br][bg*4 + 2*j + 1] = h;  Bl[br][bg*4 + 2*j + 1] = l;
        }
        __syncthreads();

        if (k0 + 32 < K) {
#pragma unroll
            for (int j = 0; j < 4; j++) xa[j] = *(const float4*)(Xp + k0 + 32 + j * 4);
#pragma unroll
            for (int j = 0; j < 2; j++) wb[j] = *(const float4*)(Wp + k0 + 32 + j * 4);
        }

#pragma unroll
        for (int step = 0; step < 2; step++) {
            const int pb = step * 8 + tig;
            unsigned ah[2][4], al[2][4];
#pragma unroll
            for (int mt = 0; mt < 2; mt++) {
                const int r = wm + mt * 16 + gid;
                ah[mt][0] = Ah[r][pb];     ah[mt][1] = Ah[r+8][pb];
                ah[mt][2] = Ah[r][pb+4];   ah[mt][3] = Ah[r+8][pb+4];
                al[mt][0] = Al[r][pb];     al[mt][1] = Al[r+8][pb];
                al[mt][2] = Al[r][pb+4];   al[mt][3] = Al[r+8][pb+4];
            }
#pragma unroll
            for (int nt = 0; nt < 4; nt++) {
                const int cn = wn + nt * 8 + gid;
                const unsigned bh0 = Bh[cn][pb], bh1 = Bh[cn][pb+4];
                const unsigned bl0 = Bl[cn][pb], bl1 = Bl[cn][pb+4];
#pragma unroll
                for (int mt = 0; mt < 2; mt++) {
                    mma16(acc[mt][nt], ah[mt][0],ah[mt][1],ah[mt][2],ah[mt][3], bh0, bh1);
                    mma16(acc[mt][nt], ah[mt][0],ah[mt][1],ah[mt][2],ah[mt][3], bl0, bl1);
                    mma16(acc[mt][nt], al[mt][0],al[mt][1],al[mt][2],al[mt][3], bh0, bh1);
                }
            }
        }
        __syncthreads();
    }

#pragma unroll
    for (int mt = 0; mt < 2; mt++) {
#pragma unroll
        for (int nt = 0; nt < 4; nt++) {
            const int r0 = m0 + wm + mt*16 + gid;
            const int r1 = r0 + 8;
            const int c  = n0 + wn + nt*8 + tig*2;
            const float b0v = bias[c], b1v = bias[c+1];
            float2 v0, v1;
            v0.x = alpha * (acc[mt][nt][0] + b0v);
            v0.y = alpha * (acc[mt][nt][1] + b1v);
            v1.x = alpha * (acc[mt][nt][2] + b0v);
            v1.y = alpha * (acc[mt][nt][3] + b1v);
            if (head_split) {
                const int h = n0 / DEP_;
                const int dd = c - n0;
                const int b0_ = r0 / S_, s0 = r0 % S_;
                const int b1_ = r1 / S_, s1 = r1 % S_;
                *(float2*)(C + (((size_t)(b0_*H_ + h))*S_ + s0)*DEP_ + dd) = v0;
                *(float2*)(C + (((size_t)(b1_*H_ + h))*S_ + s1)*DEP_ + dd) = v1;
            } else {
                *(float2*)(C + (size_t)r0 * N + c) = v0;
                *(float2*)(C + (size_t)r1 * N + c) = v1;
            }
        }
    }
}

// ======================================================================
// logits[bh,m,n] = sum_k Qp[bh,m,k]*Kp[bh,n,k]  (Q pre-scaled by 1/8)
// masked -inf where mask[b,n]==0. 128(m) x 64(n) tile, K=64 (2 slabs).
// grid (32, 16, 24)
// ======================================================================
__global__ __launch_bounds__(256, 2)
void logits_bf16(const float* __restrict__ Qp,
                 const float* __restrict__ Kp,
                 const int*   __restrict__ mask,
                 float* __restrict__ attn)
{
    __shared__ unsigned Ah[128][20], Al[128][20];
    __shared__ unsigned Bh[64][20],  Bl[64][20];
    __shared__ int smask[64];

    const int t = threadIdx.x, wid = t >> 5, lane = t & 31;
    const int gid = lane >> 2, tig = lane & 3;
    const int n0 = blockIdx.x * 64, m0 = blockIdx.y * 128;
    const int bh = blockIdx.z, b = bh / H_;
    const int wm = (wid & 3) * 32, wn = (wid >> 2) * 32;

    if (t < 64) smask[t] = mask[b * S_ + n0 + t];

    const int lr = t >> 1, lg = t & 1;
    const int br = t >> 2, bg = t & 3;

    const float* Qb = Qp + ((size_t)bh * S_ + m0 + lr) * DEP_ + lg * 16;
    const float* Kb = Kp + ((size_t)bh * S_ + n0 + br) * DEP_ + bg * 8;

    float acc[2][4][4];
#pragma unroll
    for (int i = 0; i < 2; i++)
#pragma unroll
        for (int j = 0; j < 4; j++)
#pragma unroll
            for (int q = 0; q < 4; q++) acc[i][j][q] = 0.0f;

    float4 xa[4], wb[2];
#pragma unroll
    for (int j = 0; j < 4; j++) xa[j] = *(const float4*)(Qb + j * 4);
#pragma unroll
    for (int j = 0; j < 2; j++) wb[j] = *(const float4*)(Kb + j * 4);

#pragma unroll
    for (int k0 = 0; k0 < DEP_; k0 += 32) {
#pragma unroll
        for (int j = 0; j < 4; j++) {
            unsigned h, l;
            split2(xa[j].x, xa[j].y, h, l);
            Ah[lr][lg*8 + 2*j]     = h;  Al[lr][lg*8 + 2*j]     = l;
            split2(xa[j].z, xa[j].w, h, l);
            Ah[lr][lg*8 + 2*j + 1] = h;  Al[lr][lg*8 + 2*j + 1] = l;
        }
#pragma unroll
        for (int j = 0; j < 2; j++) {
            unsigned h, l;
            split2(wb[j].x, wb[j].y, h, l);
            Bh[br][bg*4 + 2*j]     = h;  Bl[br][bg*4 + 2*j]     = l;
            split2(wb[j].z, wb[j].w, h, l);
            Bh[br][bg*4 + 2*j + 1] = h;  Bl[br][bg*4 + 2*j + 1] = l;
        }
        __syncthreads();

        if (k0 + 32 < DEP_) {
#pragma unroll
            for (int j = 0; j < 4; j++) xa[j] = *(const float4*)(Qb + k0 + 32 + j * 4);
#pragma unroll
            for (int j = 0; j < 2; j++) wb[j] = *(const float4*)(Kb + k0 + 32 + j * 4);
        }

#pragma unroll
        for (int step = 0; step < 2; step++) {
            const int pb = step * 8 + tig;
            unsigned ah[2][4], al[2][4];
#pragma unroll
            for (int mt = 0; mt < 2; mt++) {
                const int r = wm + mt * 16 + gid;
                ah[mt][0] = Ah[r][pb];     ah[mt][1] = Ah[r+8][pb];
                ah[mt][2] = Ah[r][pb+4];   ah[mt][3] = Ah[r+8][pb+4];
                al[mt][0] = Al[r][pb];     al[mt][1] = Al[r+8][pb];
                al[mt][2] = Al[r][pb+4];   al[mt][3] = Al[r+8][pb+4];
            }
#pragma unroll
            for (int nt = 0; nt < 4; nt++) {
                const int cn = wn + nt * 8 + gid;
                const unsigned bh0 = Bh[cn][pb], bh1 = Bh[cn][pb+4];
                const unsigned bl0 = Bl[cn][pb], bl1 = Bl[cn][pb+4];
#pragma unroll
                for (int mt = 0; mt < 2; mt++) {
                    mma16(acc[mt][nt], ah[mt][0],ah[mt][1],ah[mt][2],ah[mt][3], bh0, bh1);
                    mma16(acc[mt][nt], ah[mt][0],ah[mt][1],ah[mt][2],ah[mt][3], bl0, bl1);
                    mma16(acc[mt][nt], al[mt][0],al[mt][1],al[mt][2],al[mt][3], bh0, bh1);
                }
            }
        }
        __syncthreads();
    }

    float* Cb = attn + (size_t)bh * S_ * S_;
#pragma unroll
    for (int mt = 0; mt < 2; mt++) {
#pragma unroll
        for (int nt = 0; nt < 4; nt++) {
            const int r0 = m0 + wm + mt*16 + gid;
            const int r1 = r0 + 8;
            const int lc = wn + nt*8 + tig*2;
            const int c  = n0 + lc;
            const bool z0 = (smask[lc] == 0), z1 = (smask[lc+1] == 0);
            float2 v0, v1;
            v0.x = z0 ? neg_inf() : acc[mt][nt][0];
            v0.y = z1 ? neg_inf() : acc[mt][nt][1];
            v1.x = z0 ? neg_inf() : acc[mt][nt][2];
            v1.y = z1 ? neg_inf() : acc[mt][nt][3];
            *(float2*)(Cb + (size_t)r0 * S_ + c) = v0;
            *(float2*)(Cb + (size_t)r1 * S_ + c) = v1;
        }
    }
}

// ======================================================================
// Row stats over raw logits
// ======================================================================
__global__ __launch_bounds__(256)
void row_stats_kernel(const float* __restrict__ attn,
                      float* __restrict__ gmax,
                      float* __restrict__ ginv)
{
    const float* p = attn + (size_t)blockIdx.x * S_;
    const int t = threadIdx.x;

    float x[8];
    float mx = neg_inf();
#pragma unroll
    for (int i = 0; i < 8; i++) { x[i] = p[t + i*256]; mx = fmaxf(mx, x[i]); }

    __shared__ float redm[8];
    __shared__ float reds[8];

#pragma unroll
    for (int o = 16; o > 0; o >>= 1)
        mx = fmaxf(mx, __shfl_xor_sync(0xffffffffu, mx, o));
    if ((t & 31) == 0) redm[t >> 5] = mx;
    __syncthreads();
    float bm = redm[0];
#pragma unroll
    for (int i = 1; i < 8; i++) bm = fmaxf(bm, redm[i]);

    float s = 0.0f;
#pragma unroll
    for (int i = 0; i < 8; i++) s += __expf(x[i] - bm);
#pragma unroll
    for (int o = 16; o > 0; o >>= 1)
        s += __shfl_xor_sync(0xffffffffu, s, o);
    if ((t & 31) == 0) reds[t >> 5] = s;
    __syncthreads();

    if (t == 0) {
        float tot = 0.0f;
#pragma unroll
        for (int i = 0; i < 8; i++) tot += reds[i];
        gmax[blockIdx.x] = bm;
        ginv[blockIdx.x] = 1.0f / tot;
    }
}

// ======================================================================
// ctx = softmax(logits) @ V, normalizing attn in place. bf16 3-product.
// Block 128(m) x 64(d), n-slab 32 (2 k16 steps). grid (16, 24)
// V staged + transposed to k-major pairs in smem.
// ======================================================================
__global__ __launch_bounds__(256, 2)
void ctx_bf16(float* __restrict__ attn,
              const float* __restrict__ Vp,
              const float* __restrict__ gmax,
              const float* __restrict__ ginv,
              float* __restrict__ ctx)
{
    __shared__ unsigned Ah[128][20], Al[128][20];
    __shared__ float    Vst[32][68];
    __shared__ unsigned Vh[64][20], Vl[64][20];

    const int t = threadIdx.x, wid = t >> 5, lane = t & 31;
    const int gid = lane >> 2, tig = lane & 3;
    const int m0 = blockIdx.x * 128;
    const int bh = blockIdx.y;
    const int b  = bh / H_, h = bh % H_;
    const int wm = (wid & 3) * 32, wd = (wid >> 2) * 32;

    const int lr = t >> 1, lg = t & 1;       // A loader: row 0..127, half (16 n)
    const int vr = t >> 3, vg = t & 7;       // V loader: slab row 0..31, 8 d

    float* Ap = attn + ((size_t)bh * S_ + m0 + lr) * S_ + lg * 16;
    const float* Vpp = Vp + ((size_t)bh * S_ + vr) * DEP_ + vg * 8;

    const float mr = gmax[bh * S_ + m0 + lr];
    const float ir = ginv[bh * S_ + m0 + lr];

    float acc[2][4][4];
#pragma unroll
    for (int i = 0; i < 2; i++)
#pragma unroll
        for (int j = 0; j < 4; j++)
#pragma unroll
            for (int q = 0; q < 4; q++) acc[i][j][q] = 0.0f;

    float4 av[4], vv[2];
#pragma unroll
    for (int j = 0; j < 4; j++) av[j] = *(const float4*)(Ap + j * 4);
#pragma unroll
    for (int j = 0; j < 2; j++) vv[j] = *(const float4*)(Vpp + j * 4);

    for (int nc = 0; nc < S_; nc += 32) {
        // normalize A, write back, split into pairs; stage V
#pragma unroll
        for (int j = 0; j < 4; j++) {
            float4 pv;
            pv.x = __expf(av[j].x - mr) * ir;
            pv.y = __expf(av[j].y - mr) * ir;
            pv.z = __expf(av[j].z - mr) * ir;
            pv.w = __expf(av[j].w - mr) * ir;
            *(float4*)(Ap + nc + j * 4) = pv;   // final normalized attn
            unsigned hh, ll;
            split2(pv.x, pv.y, hh, ll);
            Ah[lr][lg*8 + 2*j]     = hh;  Al[lr][lg*8 + 2*j]     = ll;
            split2(pv.z, pv.w, hh, ll);
            Ah[lr][lg*8 + 2*j + 1] = hh;  Al[lr][lg*8 + 2*j + 1] = ll;
        }
#pragma unroll
        for (int j = 0; j < 2; j++)
            *(float4*)&Vst[vr][vg*8 + j*4] = vv[j];
        __syncthreads();

        // transpose V into k-major pairs; prefetch next slab
#pragma unroll
        for (int i = 0; i < 4; i++) {
            const int idx = t + i * 256;
            const int p = idx & 15;          // n-pair 0..15
            const int d = idx >> 4;          // 0..63
            unsigned hh, ll;
            split2(Vst[2*p][d], Vst[2*p + 1][d], hh, ll);
            Vh[d][p] = hh;  Vl[d][p] = ll;
        }
        if (nc + 32 < S_) {
#pragma unroll
            for (int j = 0; j < 4; j++) av[j] = *(const float4*)(Ap + nc + 32 + j * 4);
#pragma unroll
            for (int j = 0; j < 2; j++)
                vv[j] = *(const float4*)(Vpp + (size_t)(nc + 32) * DEP_ + j * 4);
        }
        __syncthreads();

#pragma unroll
        for (int step = 0; step < 2; step++) {
            const int pb = step * 8 + tig;
            unsigned ah[2][4], al[2][4];
#pragma unroll
            for (int mt = 0; mt < 2; mt++) {
                const int r = wm + mt * 16 + gid;
                ah[mt][0] = Ah[r][pb];     ah[mt][1] = Ah[r+8][pb];
                ah[mt][2] = Ah[r][pb+4];   ah[mt][3] = Ah[r+8][pb+4];
                al[mt][0] = Al[r][pb];     al[mt][1] = Al[r+8][pb];
                al[mt][2] = Al[r][pb+4];   al[mt][3] = Al[r+8][pb+4];
            }
#pragma unroll
            for (int dt = 0; dt < 4; dt++) {
                const int cd = wd + dt * 8 + gid;
                const unsigned bh0 = Vh[cd][pb], bh1 = Vh[cd][pb+4];
                const unsigned bl0 = Vl[cd][pb], bl1 = Vl[cd][pb+4];
#pragma unroll
                for (int mt = 0; mt < 2; mt++) {
                    mma16(acc[mt][dt], ah[mt][0],ah[mt][1],ah[mt][2],ah[mt][3], bh0, bh1);
                    mma16(acc[mt][dt], ah[mt][0],ah[mt][1],ah[mt][2],ah[mt][3], bl0, bl1);
                    mma16(acc[mt][dt], al[mt][0],al[mt][1],al[mt][2],al[mt][3], bh0, bh1);
                }
            }
        }
        __syncthreads();
    }

#pragma unroll
    for (int mt = 0; mt < 2; mt++) {
#pragma unroll
        for (int dt = 0; dt < 4; dt++) {
            const int r0 = m0 + wm + mt*16 + gid;
            const int r1 = r0 + 8;
            const int d  = wd + dt*8 + tig*2;
            float2 v0 = {acc[mt][dt][0], acc[mt][dt][1]};
            float2 v1 = {acc[mt][dt][2], acc[mt][dt][3]};
            *(float2*)(ctx + ((size_t)b * S_ + r0) * D_ + h * DEP_ + d) = v0;
            *(float2*)(ctx + ((size_t)b * S_ + r1) * D_ + h * DEP_ + d) = v1;
        }
    }
}

// ======================================================================
extern "C" void kernel_launch(void* const* d_in, const int* in_sizes, int n_in,
                              void* d_out, int out_size)
{
    const float* q    = (const float*)d_in[0];
    const float* k    = (const float*)d_in[1];
    const float* v    = (const float*)d_in[2];
    const int*   mask = (const int*)  d_in[3];
    const float* wq_w = (const float*)d_in[4];
    const float* wq_b = (const float*)d_in[5];
    const float* wk_w = (const float*)d_in[6];
    const float* wk_b = (const float*)d_in[7];
    const float* wv_w = (const float*)d_in[8];
    const float* wv_b = (const float*)d_in[9];
    const float* wo_w = (const float*)d_in[10];
    const float* wo_b = (const float*)d_in[11];
    float* out = (float*)d_out;

    float *Qp, *Kp, *Vp, *ctxp, *rmax, *rinv, *attn_s;
    cudaGetSymbolAddress((void**)&Qp,     g_Qp);
    cudaGetSymbolAddress((void**)&Kp,     g_Kp);
    cudaGetSymbolAddress((void**)&Vp,     g_Vp);
    cudaGetSymbolAddress((void**)&ctxp,   g_ctx);
    cudaGetSymbolAddress((void**)&rmax,   g_rowmax);
    cudaGetSymbolAddress((void**)&rinv,   g_rowinv);
    cudaGetSymbolAddress((void**)&attn_s, g_attn_scratch);

    const long long need = (long long)OUT_ELEMS + (long long)ATTN_ELEMS;
    float* attn = ((long long)out_size >= need) ? (out + OUT_ELEMS) : attn_s;

    // Q/K/V projections (Q pre-scaled by 1/sqrt(64) = 0.125)
    dim3 pgrid(D_/64, MROWS/128);
    gemm_xwT_bf16<<<pgrid, 256>>>(q, wq_w, wq_b, Qp, D_, D_, 0.125f, 1);
    gemm_xwT_bf16<<<pgrid, 256>>>(k, wk_w, wk_b, Kp, D_, D_, 1.0f, 1);
    gemm_xwT_bf16<<<pgrid, 256>>>(v, wv_w, wv_b, Vp, D_, D_, 1.0f, 1);

    // raw masked logits
    logits_bf16<<<dim3(S_/64, S_/128, BH_), 256>>>(Qp, Kp, mask, attn);

    // per-row softmax stats
    row_stats_kernel<<<dim3(BH_ * S_), 256>>>(attn, rmax, rinv);

    // ctx = softmax @ V; normalizes attn in place as it goes
    ctx_bf16<<<dim3(S_/128, BH_), 256>>>(attn, Vp, rmax, rinv, ctxp);

    // output projection
    gemm_xwT_bf16<<<pgrid, 256>>>(ctxp, wo_w, wo_b, out, D_, D_, 1.0f, 0);
}

// round 8
// speedup vs baseline: 2.1145x; 1.0003x over previous
#include <cuda_runtime.h>
#include <cuda_bf16.h>
#include <math.h>

#define B_    2
#define S_    2048
#define D_    768
#define H_    12
#define DEP_  64
#define BH_   (B_*H_)            // 24
#define MROWS (B_*S_)            // 4096
#define OUT_ELEMS (B_*S_*D_)     // 3145728
#define ATTN_ELEMS (BH_*S_*S_)   // 100663296

// ---- scratch (alloc-free, __device__ globals) ----
__device__ float g_Qp[BH_*S_*DEP_];
__device__ float g_Kp[BH_*S_*DEP_];
__device__ float g_Vp[BH_*S_*DEP_];
__device__ float g_ctx[MROWS*D_];
__device__ float g_rowmax[BH_*S_];
__device__ float g_rowinv[BH_*S_];
__device__ float g_attn_scratch[ATTN_ELEMS];

__device__ __forceinline__ float neg_inf() { return __int_as_float(0xff800000); }

// ---- bf16 split helpers ----
// x = hi + lo with hi, lo bf16; residual ~2^-17 * |x|
__device__ __forceinline__ void split2(float x, float y, unsigned& h, unsigned& l) {
    __nv_bfloat162 hv = __floats2bfloat162_rn(x, y);
    float2 hf = __bfloat1622float2(hv);
    __nv_bfloat162 lv = __floats2bfloat162_rn(x - hf.x, y - hf.y);
    h = *(unsigned*)&hv;
    l = *(unsigned*)&lv;
}

// D += A(16x16) * B(16x8), bf16 in, f32 accumulate
__device__ __forceinline__ void mma16(float* c,
                                      unsigned a0, unsigned a1, unsigned a2, unsigned a3,
                                      unsigned b0, unsigned b1) {
    asm volatile(
        "mma.sync.aligned.m16n8k16.row.col.f32.bf16.bf16.f32 "
        "{%0,%1,%2,%3}, {%4,%5,%6,%7}, {%8,%9}, {%0,%1,%2,%3};\n"
        : "+f"(c[0]), "+f"(c[1]), "+f"(c[2]), "+f"(c[3])
        : "r"(a0), "r"(a1), "r"(a2), "r"(a3), "r"(b0), "r"(b1));
}

// ======================================================================
// C[M,N] = alpha * (X[M,K] @ W[N,K]^T + bias[N])  via 3-product bf16 mma
// block tile 128(m) x 64(n), BK=32, 256 threads, warps 4(m) x 2(n),
// warp tile 32x32 (mt=2 x nt=4). head_split: write [B,H,S,DEP].
// ======================================================================
__global__ __launch_bounds__(256, 2)
void gemm_xwT_bf16(const float* __restrict__ X,
                   const float* __restrict__ W,
                   const float* __restrict__ bias,
                   float* __restrict__ C,
                   int K, int N, float alpha, int head_split)
{
    __shared__ unsigned Ah[128][20], Al[128][20];  // 16 k-pairs + pad
    __shared__ unsigned Bh[64][20],  Bl[64][20];

    const int t = threadIdx.x, wid = t >> 5, lane = t & 31;
    const int gid = lane >> 2, tig = lane & 3;
    const int n0 = blockIdx.x * 64, m0 = blockIdx.y * 128;
    const int wm = (wid & 3) * 32, wn = (wid >> 2) * 32;

    const int lr = t >> 1, lg = t & 1;   // A: row 0..127, half-row (16 floats)
    const int br = t >> 2, bg = t & 3;   // B: row 0..63, quarter-row (8 floats)

    const float* Xp = X + (size_t)(m0 + lr) * K + lg * 16;
    const float* Wp = W + (size_t)(n0 + br) * K + bg * 8;

    float acc[2][4][4];
#pragma unroll
    for (int i = 0; i < 2; i++)
#pragma unroll
        for (int j = 0; j < 4; j++)
#pragma unroll
            for (int q = 0; q < 4; q++) acc[i][j][q] = 0.0f;

    float4 xa[4], wb[2];
#pragma unroll
    for (int j = 0; j < 4; j++) xa[j] = *(const float4*)(Xp + j * 4);
#pragma unroll
    for (int j = 0; j < 2; j++) wb[j] = *(const float4*)(Wp + j * 4);

    for (int k0 = 0; k0 < K; k0 += 32) {
#pragma unroll
        for (int j = 0; j < 4; j++) {
            unsigned h, l;
            split2(xa[j].x, xa[j].y, h, l);
            Ah[lr][lg*8 + 2*j]     = h;  Al[lr][lg*8 + 2*j]     = l;
            split2(xa[j].z, xa[j].w, h, l);
            Ah[lr][lg*8 + 2*j + 1] = h;  Al[lr][lg*8 + 2*j + 1] = l;
        }
#pragma unroll
        for (int j = 0; j < 2; j++) {
            unsigned h, l;
            split2(wb[j].x, wb[j].y, h, l);
            Bh[br][bg*4 + 2*j]     = h;  Bl[br][bg*4 + 2*j]     = l;
            split2(wb[j].z, wb[j].w, h, l);
            Bh[br][bg*4 + 2*j + 1] = h;  Bl[br][bg*4 + 2*j + 1] = l;
        }
        __syncthreads();

        if (k0 + 32 < K) {
#pragma unroll
            for (int j = 0; j < 4; j++) xa[j] = *(const float4*)(Xp + k0 + 32 + j * 4);
#pragma unroll
            for (int j = 0; j < 2; j++) wb[j] = *(const float4*)(Wp + k0 + 32 + j * 4);
        }

#pragma unroll
        for (int step = 0; step < 2; step++) {
            const int pb = step * 8 + tig;
            unsigned ah[2][4], al[2][4];
#pragma unroll
            for (int mt = 0; mt < 2; mt++) {
                const int r = wm + mt * 16 + gid;
                ah[mt][0] = Ah[r][pb];     ah[mt][1] = Ah[r+8][pb];
                ah[mt][2] = Ah[r][pb+4];   ah[mt][3] = Ah[r+8][pb+4];
                al[mt][0] = Al[r][pb];     al[mt][1] = Al[r+8][pb];
                al[mt][2] = Al[r][pb+4];   al[mt][3] = Al[r+8][pb+4];
            }
#pragma unroll
            for (int nt = 0; nt < 4; nt++) {
                const int cn = wn + nt * 8 + gid;
                const unsigned bh0 = Bh[cn][pb], bh1 = Bh[cn][pb+4];
                const unsigned bl0 = Bl[cn][pb], bl1 = Bl[cn][pb+4];
#pragma unroll
                for (int mt = 0; mt < 2; mt++) {
                    mma16(acc[mt][nt], ah[mt][0],ah[mt][1],ah[mt][2],ah[mt][3], bh0, bh1);
                    mma16(acc[mt][nt], ah[mt][0],ah[mt][1],ah[mt][2],ah[mt][3], bl0, bl1);
                    mma16(acc[mt][nt], al[mt][0],al[mt][1],al[mt][2],al[mt][3], bh0, bh1);
                }
            }
        }
        __syncthreads();
    }

#pragma unroll
    for (int mt = 0; mt < 2; mt++) {
#pragma unroll
        for (int nt = 0; nt < 4; nt++) {
            const int r0 = m0 + wm + mt*16 + gid;
            const int r1 = r0 + 8;
            const int c  = n0 + wn + nt*8 + tig*2;
            const float b0v = bias[c], b1v = bias[c+1];
            float2 v0, v1;
            v0.x = alpha * (acc[mt][nt][0] + b0v);
            v0.y = alpha * (acc[mt][nt][1] + b1v);
            v1.x = alpha * (acc[mt][nt][2] + b0v);
            v1.y = alpha * (acc[mt][nt][3] + b1v);
            if (head_split) {
                const int h = n0 / DEP_;
                const int dd = c - n0;
                const int b0_ = r0 / S_, s0 = r0 % S_;
                const int b1_ = r1 / S_, s1 = r1 % S_;
                *(float2*)(C + (((size_t)(b0_*H_ + h))*S_ + s0)*DEP_ + dd) = v0;
                *(float2*)(C + (((size_t)(b1_*H_ + h))*S_ + s1)*DEP_ + dd) = v1;
            } else {
                *(float2*)(C + (size_t)r0 * N + c) = v0;
                *(float2*)(C + (size_t)r1 * N + c) = v1;
            }
        }
    }
}

// ======================================================================
// logits[bh,m,n] = sum_k Qp[bh,m,k]*Kp[bh,n,k]  (Q pre-scaled by 1/8)
// masked -inf where mask[b,n]==0. 128(m) x 64(n) tile, K=64 (2 slabs).
// grid (32, 16, 24)
// ======================================================================
__global__ __launch_bounds__(256, 2)
void logits_bf16(const float* __restrict__ Qp,
                 const float* __restrict__ Kp,
                 const int*   __restrict__ mask,
                 float* __restrict__ attn)
{
    __shared__ unsigned Ah[128][20], Al[128][20];
    __shared__ unsigned Bh[64][20],  Bl[64][20];
    __shared__ int smask[64];

    const int t = threadIdx.x, wid = t >> 5, lane = t & 31;
    const int gid = lane >> 2, tig = lane & 3;
    const int n0 = blockIdx.x * 64, m0 = blockIdx.y * 128;
    const int bh = blockIdx.z, b = bh / H_;
    const int wm = (wid & 3) * 32, wn = (wid >> 2) * 32;

    if (t < 64) smask[t] = mask[b * S_ + n0 + t];

    const int lr = t >> 1, lg = t & 1;
    const int br = t >> 2, bg = t & 3;

    const float* Qb = Qp + ((size_t)bh * S_ + m0 + lr) * DEP_ + lg * 16;
    const float* Kb = Kp + ((size_t)bh * S_ + n0 + br) * DEP_ + bg * 8;

    float acc[2][4][4];
#pragma unroll
    for (int i = 0; i < 2; i++)
#pragma unroll
        for (int j = 0; j < 4; j++)
#pragma unroll
            for (int q = 0; q < 4; q++) acc[i][j][q] = 0.0f;

    float4 xa[4], wb[2];
#pragma unroll
    for (int j = 0; j < 4; j++) xa[j] = *(const float4*)(Qb + j * 4);
#pragma unroll
    for (int j = 0; j < 2; j++) wb[j] = *(const float4*)(Kb + j * 4);

#pragma unroll
    for (int k0 = 0; k0 < DEP_; k0 += 32) {
#pragma unroll
        for (int j = 0; j < 4; j++) {
            unsigned h, l;
            split2(xa[j].x, xa[j].y, h, l);
            Ah[lr][lg*8 + 2*j]     = h;  Al[lr][lg*8 + 2*j]     = l;
            split2(xa[j].z, xa[j].w, h, l);
            Ah[lr][lg*8 + 2*j + 1] = h;  Al[lr][lg*8 + 2*j + 1] = l;
        }
#pragma unroll
        for (int j = 0; j < 2; j++) {
            unsigned h, l;
            split2(wb[j].x, wb[j].y, h, l);
            Bh[br][bg*4 + 2*j]     = h;  Bl[br][bg*4 + 2*j]     = l;
            split2(wb[j].z, wb[j].w, h, l);
            Bh[br][bg*4 + 2*j + 1] = h;  Bl[br][bg*4 + 2*j + 1] = l;
        }
        __syncthreads();

        if (k0 + 32 < DEP_) {
#pragma unroll
            for (int j = 0; j < 4; j++) xa[j] = *(const float4*)(Qb + k0 + 32 + j * 4);
#pragma unroll
            for (int j = 0; j < 2; j++) wb[j] = *(const float4*)(Kb + k0 + 32 + j * 4);
        }

#pragma unroll
        for (int step = 0; step < 2; step++) {
            const int pb = step * 8 + tig;
            unsigned ah[2][4], al[2][4];
#pragma unroll
            for (int mt = 0; mt < 2; mt++) {
                const int r = wm + mt * 16 + gid;
                ah[mt][0] = Ah[r][pb];     ah[mt][1] = Ah[r+8][pb];
                ah[mt][2] = Ah[r][pb+4];   ah[mt][3] = Ah[r+8][pb+4];
                al[mt][0] = Al[r][pb];     al[mt][1] = Al[r+8][pb];
                al[mt][2] = Al[r][pb+4];   al[mt][3] = Al[r+8][pb+4];
            }
#pragma unroll
            for (int nt = 0; nt < 4; nt++) {
                const int cn = wn + nt * 8 + gid;
                const unsigned bh0 = Bh[cn][pb], bh1 = Bh[cn][pb+4];
                const unsigned bl0 = Bl[cn][pb], bl1 = Bl[cn][pb+4];
#pragma unroll
                for (int mt = 0; mt < 2; mt++) {
                    mma16(acc[mt][nt], ah[mt][0],ah[mt][1],ah[mt][2],ah[mt][3], bh0, bh1);
                    mma16(acc[mt][nt], ah[mt][0],ah[mt][1],ah[mt][2],ah[mt][3], bl0, bl1);
                    mma16(acc[mt][nt], al[mt][0],al[mt][1],al[mt][2],al[mt][3], bh0, bh1);
                }
            }
        }
        __syncthreads();
    }

    float* Cb = attn + (size_t)bh * S_ * S_;
#pragma unroll
    for (int mt = 0; mt < 2; mt++) {
#pragma unroll
        for (int nt = 0; nt < 4; nt++) {
            const int r0 = m0 + wm + mt*16 + gid;
            const int r1 = r0 + 8;
            const int lc = wn + nt*8 + tig*2;
            const int c  = n0 + lc;
            const bool z0 = (smask[lc] == 0), z1 = (smask[lc+1] == 0);
            float2 v0, v1;
            v0.x = z0 ? neg_inf() : acc[mt][nt][0];
            v0.y = z1 ? neg_inf() : acc[mt][nt][1];
            v1.x = z0 ? neg_inf() : acc[mt][nt][2];
            v1.y = z1 ? neg_inf() : acc[mt][nt][3];
            *(float2*)(Cb + (size_t)r0 * S_ + c) = v0;
            *(float2*)(Cb + (size_t)r1 * S_ + c) = v1;
        }
    }
}

// ======================================================================
// Row stats over raw logits
// ======================================================================
__global__ __launch_bounds__(256)
void row_stats_kernel(const float* __restrict__ attn,
                      float* __restrict__ gmax,
                      float* __restrict__ ginv)
{
    const float* p = attn + (size_t)blockIdx.x * S_;
    const int t = threadIdx.x;

    float x[8];
    float mx = neg_inf();
#pragma unroll
    for (int i = 0; i < 8; i++) { x[i] = p[t + i*256]; mx = fmaxf(mx, x[i]); }

    __shared__ float redm[8];
    __shared__ float reds[8];

#pragma unroll
    for (int o = 16; o > 0; o >>= 1)
        mx = fmaxf(mx, __shfl_xor_sync(0xffffffffu, mx, o));
    if ((t & 31) == 0) redm[t >> 5] = mx;
    __syncthreads();
    float bm = redm[0];
#pragma unroll
    for (int i = 1; i < 8; i++) bm = fmaxf(bm, redm[i]);

    float s = 0.0f;
#pragma unroll
    for (int i = 0; i < 8; i++) s += __expf(x[i] - bm);
#pragma unroll
    for (int o = 16; o > 0; o >>= 1)
        s += __shfl_xor_sync(0xffffffffu, s, o);
    if ((t & 31) == 0) reds[t >> 5] = s;
    __syncthreads();

    if (t == 0) {
        float tot = 0.0f;
#pragma unroll
        for (int i = 0; i < 8; i++) tot += reds[i];
        gmax[blockIdx.x] = bm;
        ginv[blockIdx.x] = 1.0f / tot;
    }
}

// ======================================================================
// ctx = softmax(logits) @ V, normalizing attn in place. bf16 3-product.
// Block 128(m) x 64(d), n-slab 32 (2 k16 steps). grid (16, 24)
// V staged + transposed to k-major pairs in smem.
// ======================================================================
__global__ __launch_bounds__(256, 2)
void ctx_bf16(float* __restrict__ attn,
              const float* __restrict__ Vp,
              const float* __restrict__ gmax,
              const float* __restrict__ ginv,
              float* __restrict__ ctx)
{
    __shared__ unsigned Ah[128][20], Al[128][20];
    __shared__ float    Vst[32][68];
    __shared__ unsigned Vh[64][20], Vl[64][20];

    const int t = threadIdx.x, wid = t >> 5, lane = t & 31;
    const int gid = lane >> 2, tig = lane & 3;
    const int m0 = blockIdx.x * 128;
    const int bh = blockIdx.y;
    const int b  = bh / H_, h = bh % H_;
    const int wm = (wid & 3) * 32, wd = (wid >> 2) * 32;

    const int lr = t >> 1, lg = t & 1;       // A loader: row 0..127, half (16 n)
    const int vr = t >> 3, vg = t & 7;       // V loader: slab row 0..31, 8 d

    float* Ap = attn + ((size_t)bh * S_ + m0 + lr) * S_ + lg * 16;
    const float* Vpp = Vp + ((size_t)bh * S_ + vr) * DEP_ + vg * 8;

    const float mr = gmax[bh * S_ + m0 + lr];
    const float ir = ginv[bh * S_ + m0 + lr];

    float acc[2][4][4];
#pragma unroll
    for (int i = 0; i < 2; i++)
#pragma unroll
        for (int j = 0; j < 4; j++)
#pragma unroll
            for (int q = 0; q < 4; q++) acc[i][j][q] = 0.0f;

    float4 av[4], vv[2];
#pragma unroll
    for (int j = 0; j < 4; j++) av[j] = *(const float4*)(Ap + j * 4);
#pragma unroll
    for (int j = 0; j < 2; j++) vv[j] = *(const float4*)(Vpp + j * 4);

    for (int nc = 0; nc < S_; nc += 32) {
        // normalize A, write back, split into pairs; stage V
#pragma unroll
        for (int j = 0; j < 4; j++) {
            float4 pv;
            pv.x = __expf(av[j].x - mr) * ir;
            pv.y = __expf(av[j].y - mr) * ir;
            pv.z = __expf(av[j].z - mr) * ir;
            pv.w = __expf(av[j].w - mr) * ir;
            *(float4*)(Ap + nc + j * 4) = pv;   // final normalized attn
            unsigned hh, ll;
            split2(pv.x, pv.y, hh, ll);
            Ah[lr][lg*8 + 2*j]     = hh;  Al[lr][lg*8 + 2*j]     = ll;
            split2(pv.z, pv.w, hh, ll);
            Ah[lr][lg*8 + 2*j + 1] = hh;  Al[lr][lg*8 + 2*j + 1] = ll;
        }
#pragma unroll
        for (int j = 0; j < 2; j++)
            *(float4*)&Vst[vr][vg*8 + j*4] = vv[j];
        __syncthreads();

        // transpose V into k-major pairs; prefetch next slab
#pragma unroll
        for (int i = 0; i < 4; i++) {
            const int idx = t + i * 256;
            const int p = idx & 15;          // n-pair 0..15
            const int d = idx >> 4;          // 0..63
            unsigned hh, ll;
            split2(Vst[2*p][d], Vst[2*p + 1][d], hh, ll);
            Vh[d][p] = hh;  Vl[d][p] = ll;
        }
        if (nc + 32 < S_) {
#pragma unroll
            for (int j = 0; j < 4; j++) av[j] = *(const float4*)(Ap + nc + 32 + j * 4);
#pragma unroll
            for (int j = 0; j < 2; j++)
                vv[j] = *(const float4*)(Vpp + (size_t)(nc + 32) * DEP_ + j * 4);
        }
        __syncthreads();

#pragma unroll
        for (int step = 0; step < 2; step++) {
            const int pb = step * 8 + tig;
            unsigned ah[2][4], al[2][4];
#pragma unroll
            for (int mt = 0; mt < 2; mt++) {
                const int r = wm + mt * 16 + gid;
                ah[mt][0] = Ah[r][pb];     ah[mt][1] = Ah[r+8][pb];
                ah[mt][2] = Ah[r][pb+4];   ah[mt][3] = Ah[r+8][pb+4];
                al[mt][0] = Al[r][pb];     al[mt][1] = Al[r+8][pb];
                al[mt][2] = Al[r][pb+4];   al[mt][3] = Al[r+8][pb+4];
            }
#pragma unroll
            for (int dt = 0; dt < 4; dt++) {
                const int cd = wd + dt * 8 + gid;
                const unsigned bh0 = Vh[cd][pb], bh1 = Vh[cd][pb+4];
                const unsigned bl0 = Vl[cd][pb], bl1 = Vl[cd][pb+4];
#pragma unroll
                for (int mt = 0; mt < 2; mt++) {
                    mma16(acc[mt][dt], ah[mt][0],ah[mt][1],ah[mt][2],ah[mt][3], bh0, bh1);
                    mma16(acc[mt][dt], ah[mt][0],ah[mt][1],ah[mt][2],ah[mt][3], bl0, bl1);
                    mma16(acc[mt][dt], al[mt][0],al[mt][1],al[mt][2],al[mt][3], bh0, bh1);
                }
            }
        }
        __syncthreads();
    }

#pragma unroll
    for (int mt = 0; mt < 2; mt++) {
#pragma unroll
        for (int dt = 0; dt < 4; dt++) {
            const int r0 = m0 + wm + mt*16 + gid;
            const int r1 = r0 + 8;
            const int d  = wd + dt*8 + tig*2;
            float2 v0 = {acc[mt][dt][0], acc[mt][dt][1]};
            float2 v1 = {acc[mt][dt][2], acc[mt][dt][3]};
            *(float2*)(ctx + ((size_t)b * S_ + r0) * D_ + h * DEP_ + d) = v0;
            *(float2*)(ctx + ((size_t)b * S_ + r1) * D_ + h * DEP_ + d) = v1;
        }
    }
}

// ======================================================================
extern "C" void kernel_launch(void* const* d_in, const int* in_sizes, int n_in,
                              void* d_out, int out_size)
{
    const float* q    = (const float*)d_in[0];
    const float* k    = (const float*)d_in[1];
    const float* v    = (const float*)d_in[2];
    const int*   mask = (const int*)  d_in[3];
    const float* wq_w = (const float*)d_in[4];
    const float* wq_b = (const float*)d_in[5];
    const float* wk_w = (const float*)d_in[6];
    const float* wk_b = (const float*)d_in[7];
    const float* wv_w = (const float*)d_in[8];
    const float* wv_b = (const float*)d_in[9];
    const float* wo_w = (const float*)d_in[10];
    const float* wo_b = (const float*)d_in[11];
    float* out = (float*)d_out;

    float *Qp, *Kp, *Vp, *ctxp, *rmax, *rinv, *attn_s;
    cudaGetSymbolAddress((void**)&Qp,     g_Qp);
    cudaGetSymbolAddress((void**)&Kp,     g_Kp);
    cudaGetSymbolAddress((void**)&Vp,     g_Vp);
    cudaGetSymbolAddress((void**)&ctxp,   g_ctx);
    cudaGetSymbolAddress((void**)&rmax,   g_rowmax);
    cudaGetSymbolAddress((void**)&rinv,   g_rowinv);
    cudaGetSymbolAddress((void**)&attn_s, g_attn_scratch);

    const long long need = (long long)OUT_ELEMS + (long long)ATTN_ELEMS;
    float* attn = ((long long)out_size >= need) ? (out + OUT_ELEMS) : attn_s;

    // Q/K/V projections (Q pre-scaled by 1/sqrt(64) = 0.125)
    dim3 pgrid(D_/64, MROWS/128);
    gemm_xwT_bf16<<<pgrid, 256>>>(q, wq_w, wq_b, Qp, D_, D_, 0.125f, 1);
    gemm_xwT_bf16<<<pgrid, 256>>>(k, wk_w, wk_b, Kp, D_, D_, 1.0f, 1);
    gemm_xwT_bf16<<<pgrid, 256>>>(v, wv_w, wv_b, Vp, D_, D_, 1.0f, 1);

    // raw masked logits
    logits_bf16<<<dim3(S_/64, S_/128, BH_), 256>>>(Qp, Kp, mask, attn);

    // per-row softmax stats
    row_stats_kernel<<<dim3(BH_ * S_), 256>>>(attn, rmax, rinv);

    // ctx = softmax @ V; normalizes attn in place as it goes
    ctx_bf16<<<dim3(S_/128, BH_), 256>>>(attn, Vp, rmax, rinv, ctxp);

    // output projection
    gemm_xwT_bf16<<<pgrid, 256>>>(ctxp, wo_w, wo_b, out, D_, D_, 1.0f, 0);
}

// round 9
// speedup vs baseline: 2.2429x; 1.0607x over previous
#include <cuda_runtime.h>
#include <cuda_bf16.h>
#include <math.h>

#define B_    2
#define S_    2048
#define D_    768
#define H_    12
#define DEP_  64
#define BH_   (B_*H_)            // 24
#define MROWS (B_*S_)            // 4096
#define OUT_ELEMS (B_*S_*D_)     // 3145728
#define ATTN_ELEMS (BH_*S_*S_)   // 100663296

// ---- scratch (alloc-free, __device__ globals) ----
__device__ float g_Qp[BH_*S_*DEP_];
__device__ float g_Kp[BH_*S_*DEP_];
__device__ float g_Vp[BH_*S_*DEP_];
__device__ float g_ctx[MROWS*D_];
__device__ float g_rowmax[BH_*S_];
__device__ float g_rowinv[BH_*S_];
__device__ float g_attn_scratch[ATTN_ELEMS];

__device__ __forceinline__ float neg_inf() { return __int_as_float(0xff800000); }

// ---- bf16 split helpers ----
__device__ __forceinline__ void split2(float x, float y, unsigned& h, unsigned& l) {
    __nv_bfloat162 hv = __floats2bfloat162_rn(x, y);
    float2 hf = __bfloat1622float2(hv);
    __nv_bfloat162 lv = __floats2bfloat162_rn(x - hf.x, y - hf.y);
    h = *(unsigned*)&hv;
    l = *(unsigned*)&lv;
}

// D += A(16x16) * B(16x8), bf16 in, f32 accumulate
__device__ __forceinline__ void mma16(float* c,
                                      unsigned a0, unsigned a1, unsigned a2, unsigned a3,
                                      unsigned b0, unsigned b1) {
    asm volatile(
        "mma.sync.aligned.m16n8k16.row.col.f32.bf16.bf16.f32 "
        "{%0,%1,%2,%3}, {%4,%5,%6,%7}, {%8,%9}, {%0,%1,%2,%3};\n"
        : "+f"(c[0]), "+f"(c[1]), "+f"(c[2]), "+f"(c[3])
        : "r"(a0), "r"(a1), "r"(a2), "r"(a3), "r"(b0), "r"(b1));
}

__device__ __forceinline__ void ldsm_x4(unsigned* r, const void* p) {
    unsigned addr = (unsigned)__cvta_generic_to_shared(p);
    asm volatile("ldmatrix.sync.aligned.m8n8.x4.shared.b16 {%0,%1,%2,%3}, [%4];"
        : "=r"(r[0]), "=r"(r[1]), "=r"(r[2]), "=r"(r[3]) : "r"(addr));
}

// Per-lane ldmatrix address offsets (rows in [.][20]-unsigned layout):
// A tile (16m x 16k): lanes 0-7 m0-7/k0-7, 8-15 m8-15/k0-7,
//                     16-23 m0-7/k8-15, 24-31 m8-15/k8-15
//   -> row = base + (lane&15), col(unsigned) = kc + ((lane>>4)&1)*4
// B pair tile (16n x 16k): lanes 0-7 n0-7/k0-7, 8-15 n0-7/k8-15,
//                          16-23 n8-15/k0-7, 24-31 n8-15/k8-15
//   -> row = base + (lane&7) + ((lane>>4)&1)*8, col = kc + ((lane>>3)&1)*4

// ======================================================================
// C[M,N] = alpha * (X[M,K] @ W[N,K]^T + bias[N])  via 3-product bf16 mma
// block tile 128(m) x 64(n), BK=32, 256 threads, warps 4(m) x 2(n)
// ======================================================================
__global__ __launch_bounds__(256, 2)
void gemm_xwT_bf16(const float* __restrict__ X,
                   const float* __restrict__ W,
                   const float* __restrict__ bias,
                   float* __restrict__ C,
                   int K, int N, float alpha, int head_split)
{
    __shared__ unsigned Ah[128][20], Al[128][20];
    __shared__ unsigned Bh[64][20],  Bl[64][20];

    const int t = threadIdx.x, wid = t >> 5, lane = t & 31;
    const int gid = lane >> 2, tig = lane & 3;
    const int n0 = blockIdx.x * 64, m0 = blockIdx.y * 128;
    const int wm = (wid & 3) * 32, wn = (wid >> 2) * 32;

    const int a_r = lane & 15, a_c = ((lane >> 4) & 1) * 4;
    const int b_r = (lane & 7) + ((lane >> 4) & 1) * 8;
    const int b_c = ((lane >> 3) & 1) * 4;

    const int lr = t >> 1, lg = t & 1;
    const int br = t >> 2, bg = t & 3;

    const float* Xp = X + (size_t)(m0 + lr) * K + lg * 16;
    const float* Wp = W + (size_t)(n0 + br) * K + bg * 8;

    float acc[2][4][4];
#pragma unroll
    for (int i = 0; i < 2; i++)
#pragma unroll
        for (int j = 0; j < 4; j++)
#pragma unroll
            for (int q = 0; q < 4; q++) acc[i][j][q] = 0.0f;

    float4 xa[4], wb[2];
#pragma unroll
    for (int j = 0; j < 4; j++) xa[j] = *(const float4*)(Xp + j * 4);
#pragma unroll
    for (int j = 0; j < 2; j++) wb[j] = *(const float4*)(Wp + j * 4);

    for (int k0 = 0; k0 < K; k0 += 32) {
#pragma unroll
        for (int j = 0; j < 4; j++) {
            unsigned h, l;
            split2(xa[j].x, xa[j].y, h, l);
            Ah[lr][lg*8 + 2*j]     = h;  Al[lr][lg*8 + 2*j]     = l;
            split2(xa[j].z, xa[j].w, h, l);
            Ah[lr][lg*8 + 2*j + 1] = h;  Al[lr][lg*8 + 2*j + 1] = l;
        }
#pragma unroll
        for (int j = 0; j < 2; j++) {
            unsigned h, l;
            split2(wb[j].x, wb[j].y, h, l);
            Bh[br][bg*4 + 2*j]     = h;  Bl[br][bg*4 + 2*j]     = l;
            split2(wb[j].z, wb[j].w, h, l);
            Bh[br][bg*4 + 2*j + 1] = h;  Bl[br][bg*4 + 2*j + 1] = l;
        }
        __syncthreads();

        if (k0 + 32 < K) {
#pragma unroll
            for (int j = 0; j < 4; j++) xa[j] = *(const float4*)(Xp + k0 + 32 + j * 4);
#pragma unroll
            for (int j = 0; j < 2; j++) wb[j] = *(const float4*)(Wp + k0 + 32 + j * 4);
        }

#pragma unroll
        for (int step = 0; step < 2; step++) {
            const int kc = step * 8;
            unsigned ah[2][4], al[2][4], bhf[2][4], blf[2][4];
#pragma unroll
            for (int mt = 0; mt < 2; mt++) {
                ldsm_x4(ah[mt], &Ah[wm + mt*16 + a_r][kc + a_c]);
                ldsm_x4(al[mt], &Al[wm + mt*16 + a_r][kc + a_c]);
            }
#pragma unroll
            for (int np = 0; np < 2; np++) {
                ldsm_x4(bhf[np], &Bh[wn + np*16 + b_r][kc + b_c]);
                ldsm_x4(blf[np], &Bl[wn + np*16 + b_r][kc + b_c]);
            }
#pragma unroll
            for (int nt = 0; nt < 4; nt++) {
                const unsigned bh0 = bhf[nt>>1][(nt&1)*2], bh1 = bhf[nt>>1][(nt&1)*2+1];
                const unsigned bl0 = blf[nt>>1][(nt&1)*2], bl1 = blf[nt>>1][(nt&1)*2+1];
#pragma unroll
                for (int mt = 0; mt < 2; mt++) {
                    mma16(acc[mt][nt], ah[mt][0],ah[mt][1],ah[mt][2],ah[mt][3], bh0, bh1);
                    mma16(acc[mt][nt], ah[mt][0],ah[mt][1],ah[mt][2],ah[mt][3], bl0, bl1);
                    mma16(acc[mt][nt], al[mt][0],al[mt][1],al[mt][2],al[mt][3], bh0, bh1);
                }
            }
        }
        __syncthreads();
    }

#pragma unroll
    for (int mt = 0; mt < 2; mt++) {
#pragma unroll
        for (int nt = 0; nt < 4; nt++) {
            const int r0 = m0 + wm + mt*16 + gid;
            const int r1 = r0 + 8;
            const int c  = n0 + wn + nt*8 + tig*2;
            const float b0v = bias[c], b1v = bias[c+1];
            float2 v0, v1;
            v0.x = alpha * (acc[mt][nt][0] + b0v);
            v0.y = alpha * (acc[mt][nt][1] + b1v);
            v1.x = alpha * (acc[mt][nt][2] + b0v);
            v1.y = alpha * (acc[mt][nt][3] + b1v);
            if (head_split) {
                const int h = n0 / DEP_;
                const int dd = c - n0;
                const int b0_ = r0 / S_, s0 = r0 % S_;
                const int b1_ = r1 / S_, s1 = r1 % S_;
                *(float2*)(C + (((size_t)(b0_*H_ + h))*S_ + s0)*DEP_ + dd) = v0;
                *(float2*)(C + (((size_t)(b1_*H_ + h))*S_ + s1)*DEP_ + dd) = v1;
            } else {
                *(float2*)(C + (size_t)r0 * N + c) = v0;
                *(float2*)(C + (size_t)r1 * N + c) = v1;
            }
        }
    }
}

// ======================================================================
// logits: 128(m) x 64(n) tile, K=64. grid (32, 16, 24)
// ======================================================================
__global__ __launch_bounds__(256, 2)
void logits_bf16(const float* __restrict__ Qp,
                 const float* __restrict__ Kp,
                 const int*   __restrict__ mask,
                 float* __restrict__ attn)
{
    __shared__ unsigned Ah[128][20], Al[128][20];
    __shared__ unsigned Bh[64][20],  Bl[64][20];
    __shared__ int smask[64];

    const int t = threadIdx.x, wid = t >> 5, lane = t & 31;
    const int gid = lane >> 2, tig = lane & 3;
    const int n0 = blockIdx.x * 64, m0 = blockIdx.y * 128;
    const int bh = blockIdx.z, b = bh / H_;
    const int wm = (wid & 3) * 32, wn = (wid >> 2) * 32;

    const int a_r = lane & 15, a_c = ((lane >> 4) & 1) * 4;
    const int b_r = (lane & 7) + ((lane >> 4) & 1) * 8;
    const int b_c = ((lane >> 3) & 1) * 4;

    if (t < 64) smask[t] = mask[b * S_ + n0 + t];

    const int lr = t >> 1, lg = t & 1;
    const int br = t >> 2, bg = t & 3;

    const float* Qb = Qp + ((size_t)bh * S_ + m0 + lr) * DEP_ + lg * 16;
    const float* Kb = Kp + ((size_t)bh * S_ + n0 + br) * DEP_ + bg * 8;

    float acc[2][4][4];
#pragma unroll
    for (int i = 0; i < 2; i++)
#pragma unroll
        for (int j = 0; j < 4; j++)
#pragma unroll
            for (int q = 0; q < 4; q++) acc[i][j][q] = 0.0f;

    float4 xa[4], wb[2];
#pragma unroll
    for (int j = 0; j < 4; j++) xa[j] = *(const float4*)(Qb + j * 4);
#pragma unroll
    for (int j = 0; j < 2; j++) wb[j] = *(const float4*)(Kb + j * 4);

#pragma unroll
    for (int k0 = 0; k0 < DEP_; k0 += 32) {
#pragma unroll
        for (int j = 0; j < 4; j++) {
            unsigned h, l;
            split2(xa[j].x, xa[j].y, h, l);
            Ah[lr][lg*8 + 2*j]     = h;  Al[lr][lg*8 + 2*j]     = l;
            split2(xa[j].z, xa[j].w, h, l);
            Ah[lr][lg*8 + 2*j + 1] = h;  Al[lr][lg*8 + 2*j + 1] = l;
        }
#pragma unroll
        for (int j = 0; j < 2; j++) {
            unsigned h, l;
            split2(wb[j].x, wb[j].y, h, l);
            Bh[br][bg*4 + 2*j]     = h;  Bl[br][bg*4 + 2*j]     = l;
            split2(wb[j].z, wb[j].w, h, l);
            Bh[br][bg*4 + 2*j + 1] = h;  Bl[br][bg*4 + 2*j + 1] = l;
        }
        __syncthreads();

        if (k0 + 32 < DEP_) {
#pragma unroll
            for (int j = 0; j < 4; j++) xa[j] = *(const float4*)(Qb + k0 + 32 + j * 4);
#pragma unroll
            for (int j = 0; j < 2; j++) wb[j] = *(const float4*)(Kb + k0 + 32 + j * 4);
        }

#pragma unroll
        for (int step = 0; step < 2; step++) {
            const int kc = step * 8;
            unsigned ah[2][4], al[2][4], bhf[2][4], blf[2][4];
#pragma unroll
            for (int mt = 0; mt < 2; mt++) {
                ldsm_x4(ah[mt], &Ah[wm + mt*16 + a_r][kc + a_c]);
                ldsm_x4(al[mt], &Al[wm + mt*16 + a_r][kc + a_c]);
            }
#pragma unroll
            for (int np = 0; np < 2; np++) {
                ldsm_x4(bhf[np], &Bh[wn + np*16 + b_r][kc + b_c]);
                ldsm_x4(blf[np], &Bl[wn + np*16 + b_r][kc + b_c]);
            }
#pragma unroll
            for (int nt = 0; nt < 4; nt++) {
                const unsigned bh0 = bhf[nt>>1][(nt&1)*2], bh1 = bhf[nt>>1][(nt&1)*2+1];
                const unsigned bl0 = blf[nt>>1][(nt&1)*2], bl1 = blf[nt>>1][(nt&1)*2+1];
#pragma unroll
                for (int mt = 0; mt < 2; mt++) {
                    mma16(acc[mt][nt], ah[mt][0],ah[mt][1],ah[mt][2],ah[mt][3], bh0, bh1);
                    mma16(acc[mt][nt], ah[mt][0],ah[mt][1],ah[mt][2],ah[mt][3], bl0, bl1);
                    mma16(acc[mt][nt], al[mt][0],al[mt][1],al[mt][2],al[mt][3], bh0, bh1);
                }
            }
        }
        __syncthreads();
    }

    float* Cb = attn + (size_t)bh * S_ * S_;
#pragma unroll
    for (int mt = 0; mt < 2; mt++) {
#pragma unroll
        for (int nt = 0; nt < 4; nt++) {
            const int r0 = m0 + wm + mt*16 + gid;
            const int r1 = r0 + 8;
            const int lc = wn + nt*8 + tig*2;
            const int c  = n0 + lc;
            const bool z0 = (smask[lc] == 0), z1 = (smask[lc+1] == 0);
            float2 v0, v1;
            v0.x = z0 ? neg_inf() : acc[mt][nt][0];
            v0.y = z1 ? neg_inf() : acc[mt][nt][1];
            v1.x = z0 ? neg_inf() : acc[mt][nt][2];
            v1.y = z1 ? neg_inf() : acc[mt][nt][3];
            *(float2*)(Cb + (size_t)r0 * S_ + c) = v0;
            *(float2*)(Cb + (size_t)r1 * S_ + c) = v1;
        }
    }
}

// ======================================================================
// Row stats over raw logits
// ======================================================================
__global__ __launch_bounds__(256)
void row_stats_kernel(const float* __restrict__ attn,
                      float* __restrict__ gmax,
                      float* __restrict__ ginv)
{
    const float* p = attn + (size_t)blockIdx.x * S_;
    const int t = threadIdx.x;

    float x[8];
    float mx = neg_inf();
#pragma unroll
    for (int i = 0; i < 8; i++) { x[i] = p[t + i*256]; mx = fmaxf(mx, x[i]); }

    __shared__ float redm[8];
    __shared__ float reds[8];

#pragma unroll
    for (int o = 16; o > 0; o >>= 1)
        mx = fmaxf(mx, __shfl_xor_sync(0xffffffffu, mx, o));
    if ((t & 31) == 0) redm[t >> 5] = mx;
    __syncthreads();
    float bm = redm[0];
#pragma unroll
    for (int i = 1; i < 8; i++) bm = fmaxf(bm, redm[i]);

    float s = 0.0f;
#pragma unroll
    for (int i = 0; i < 8; i++) s += __expf(x[i] - bm);
#pragma unroll
    for (int o = 16; o > 0; o >>= 1)
        s += __shfl_xor_sync(0xffffffffu, s, o);
    if ((t & 31) == 0) reds[t >> 5] = s;
    __syncthreads();

    if (t == 0) {
        float tot = 0.0f;
#pragma unroll
        for (int i = 0; i < 8; i++) tot += reds[i];
        gmax[blockIdx.x] = bm;
        ginv[blockIdx.x] = 1.0f / tot;
    }
}

// ======================================================================
// ctx = softmax(logits) @ V, normalizing attn in place.
// Block 128(m) x 64(d), n-slab 32. grid (16, 24)
// ======================================================================
__global__ __launch_bounds__(256, 2)
void ctx_bf16(float* __restrict__ attn,
              const float* __restrict__ Vp,
              const float* __restrict__ gmax,
              const float* __restrict__ ginv,
              float* __restrict__ ctx)
{
    __shared__ unsigned Ah[128][20], Al[128][20];
    __shared__ float    Vst[32][68];
    __shared__ unsigned Vh[64][20], Vl[64][20];

    const int t = threadIdx.x, wid = t >> 5, lane = t & 31;
    const int gid = lane >> 2, tig = lane & 3;
    const int m0 = blockIdx.x * 128;
    const int bh = blockIdx.y;
    const int b  = bh / H_, h = bh % H_;
    const int wm = (wid & 3) * 32, wd = (wid >> 2) * 32;

    const int a_r = lane & 15, a_c = ((lane >> 4) & 1) * 4;
    const int b_r = (lane & 7) + ((lane >> 4) & 1) * 8;
    const int b_c = ((lane >> 3) & 1) * 4;

    const int lr = t >> 1, lg = t & 1;
    const int vr = t >> 3, vg = t & 7;

    float* Ap = attn + ((size_t)bh * S_ + m0 + lr) * S_ + lg * 16;
    const float* Vpp = Vp + ((size_t)bh * S_ + vr) * DEP_ + vg * 8;

    const float mr = gmax[bh * S_ + m0 + lr];
    const float ir = ginv[bh * S_ + m0 + lr];

    float acc[2][4][4];
#pragma unroll
    for (int i = 0; i < 2; i++)
#pragma unroll
        for (int j = 0; j < 4; j++)
#pragma unroll
            for (int q = 0; q < 4; q++) acc[i][j][q] = 0.0f;

    float4 av[4], vv[2];
#pragma unroll
    for (int j = 0; j < 4; j++) av[j] = *(const float4*)(Ap + j * 4);
#pragma unroll
    for (int j = 0; j < 2; j++) vv[j] = *(const float4*)(Vpp + j * 4);

    for (int nc = 0; nc < S_; nc += 32) {
#pragma unroll
        for (int j = 0; j < 4; j++) {
            float4 pv;
            pv.x = __expf(av[j].x - mr) * ir;
            pv.y = __expf(av[j].y - mr) * ir;
            pv.z = __expf(av[j].z - mr) * ir;
            pv.w = __expf(av[j].w - mr) * ir;
            *(float4*)(Ap + nc + j * 4) = pv;   // final normalized attn
            unsigned hh, ll;
            split2(pv.x, pv.y, hh, ll);
            Ah[lr][lg*8 + 2*j]     = hh;  Al[lr][lg*8 + 2*j]     = ll;
            split2(pv.z, pv.w, hh, ll);
            Ah[lr][lg*8 + 2*j + 1] = hh;  Al[lr][lg*8 + 2*j + 1] = ll;
        }
#pragma unroll
        for (int j = 0; j < 2; j++)
            *(float4*)&Vst[vr][vg*8 + j*4] = vv[j];
        __syncthreads();

#pragma unroll
        for (int i = 0; i < 4; i++) {
            const int idx = t + i * 256;
            const int p = idx & 15;
            const int d = idx >> 4;
            unsigned hh, ll;
            split2(Vst[2*p][d], Vst[2*p + 1][d], hh, ll);
            Vh[d][p] = hh;  Vl[d][p] = ll;
        }
        if (nc + 32 < S_) {
#pragma unroll
            for (int j = 0; j < 4; j++) av[j] = *(const float4*)(Ap + nc + 32 + j * 4);
#pragma unroll
            for (int j = 0; j < 2; j++)
                vv[j] = *(const float4*)(Vpp + (size_t)(nc + 32) * DEP_ + j * 4);
        }
        __syncthreads();

#pragma unroll
        for (int step = 0; step < 2; step++) {
            const int kc = step * 8;
            unsigned ah[2][4], al[2][4], bhf[2][4], blf[2][4];
#pragma unroll
            for (int mt = 0; mt < 2; mt++) {
                ldsm_x4(ah[mt], &Ah[wm + mt*16 + a_r][kc + a_c]);
                ldsm_x4(al[mt], &Al[wm + mt*16 + a_r][kc + a_c]);
            }
#pragma unroll
            for (int np = 0; np < 2; np++) {
                ldsm_x4(bhf[np], &Vh[wd + np*16 + b_r][kc + b_c]);
                ldsm_x4(blf[np], &Vl[wd + np*16 + b_r][kc + b_c]);
            }
#pragma unroll
            for (int dt = 0; dt < 4; dt++) {
                const unsigned bh0 = bhf[dt>>1][(dt&1)*2], bh1 = bhf[dt>>1][(dt&1)*2+1];
                const unsigned bl0 = blf[dt>>1][(dt&1)*2], bl1 = blf[dt>>1][(dt&1)*2+1];
#pragma unroll
                for (int mt = 0; mt < 2; mt++) {
                    mma16(acc[mt][dt], ah[mt][0],ah[mt][1],ah[mt][2],ah[mt][3], bh0, bh1);
                    mma16(acc[mt][dt], ah[mt][0],ah[mt][1],ah[mt][2],ah[mt][3], bl0, bl1);
                    mma16(acc[mt][dt], al[mt][0],al[mt][1],al[mt][2],al[mt][3], bh0, bh1);
                }
            }
        }
        __syncthreads();
    }

#pragma unroll
    for (int mt = 0; mt < 2; mt++) {
#pragma unroll
        for (int dt = 0; dt < 4; dt++) {
            const int r0 = m0 + wm + mt*16 + gid;
            const int r1 = r0 + 8;
            const int d  = wd + dt*8 + tig*2;
            float2 v0 = {acc[mt][dt][0], acc[mt][dt][1]};
            float2 v1 = {acc[mt][dt][2], acc[mt][dt][3]};
            *(float2*)(ctx + ((size_t)b * S_ + r0) * D_ + h * DEP_ + d) = v0;
            *(float2*)(ctx + ((size_t)b * S_ + r1) * D_ + h * DEP_ + d) = v1;
        }
    }
}

// ======================================================================
extern "C" void kernel_launch(void* const* d_in, const int* in_sizes, int n_in,
                              void* d_out, int out_size)
{
    const float* q    = (const float*)d_in[0];
    const float* k    = (const float*)d_in[1];
    const float* v    = (const float*)d_in[2];
    const int*   mask = (const int*)  d_in[3];
    const float* wq_w = (const float*)d_in[4];
    const float* wq_b = (const float*)d_in[5];
    const float* wk_w = (const float*)d_in[6];
    const float* wk_b = (const float*)d_in[7];
    const float* wv_w = (const float*)d_in[8];
    const float* wv_b = (const float*)d_in[9];
    const float* wo_w = (const float*)d_in[10];
    const float* wo_b = (const float*)d_in[11];
    float* out = (float*)d_out;

    float *Qp, *Kp, *Vp, *ctxp, *rmax, *rinv, *attn_s;
    cudaGetSymbolAddress((void**)&Qp,     g_Qp);
    cudaGetSymbolAddress((void**)&Kp,     g_Kp);
    cudaGetSymbolAddress((void**)&Vp,     g_Vp);
    cudaGetSymbolAddress((void**)&ctxp,   g_ctx);
    cudaGetSymbolAddress((void**)&rmax,   g_rowmax);
    cudaGetSymbolAddress((void**)&rinv,   g_rowinv);
    cudaGetSymbolAddress((void**)&attn_s, g_attn_scratch);

    const long long need = (long long)OUT_ELEMS + (long long)ATTN_ELEMS;
    float* attn = ((long long)out_size >= need) ? (out + OUT_ELEMS) : attn_s;

    // Q/K/V projections (Q pre-scaled by 1/sqrt(64) = 0.125)
    dim3 pgrid(D_/64, MROWS/128);
    gemm_xwT_bf16<<<pgrid, 256>>>(q, wq_w, wq_b, Qp, D_, D_, 0.125f, 1);
    gemm_xwT_bf16<<<pgrid, 256>>>(k, wk_w, wk_b, Kp, D_, D_, 1.0f, 1);
    gemm_xwT_bf16<<<pgrid, 256>>>(v, wv_w, wv_b, Vp, D_, D_, 1.0f, 1);

    // raw masked logits
    logits_bf16<<<dim3(S_/64, S_/128, BH_), 256>>>(Qp, Kp, mask, attn);

    // per-row softmax stats
    row_stats_kernel<<<dim3(BH_ * S_), 256>>>(attn, rmax, rinv);

    // ctx = softmax @ V; normalizes attn in place as it goes
    ctx_bf16<<<dim3(S_/128, BH_), 256>>>(attn, Vp, rmax, rinv, ctxp);

    // output projection
    gemm_xwT_bf16<<<pgrid, 256>>>(ctxp, wo_w, wo_b, out, D_, D_, 1.0f, 0);
}

// round 10
// speedup vs baseline: 2.2834x; 1.0181x over previous
#include <cuda_runtime.h>
#include <cuda_bf16.h>
#include <math.h>

#define B_    2
#define S_    2048
#define D_    768
#define H_    12
#define DEP_  64
#define BH_   (B_*H_)            // 24
#define MROWS (B_*S_)            // 4096
#define OUT_ELEMS (B_*S_*D_)     // 3145728
#define ATTN_ELEMS (BH_*S_*S_)   // 100663296
#define NCHUNK 8                 // 2048 / 256 stat chunks

// ---- scratch (alloc-free, __device__ globals) ----
__device__ float g_Qp[BH_*S_*DEP_];
__device__ float g_Kp[BH_*S_*DEP_];
__device__ float g_Vp[BH_*S_*DEP_];
__device__ float g_ctx[MROWS*D_];
__device__ float g_rowmax[BH_*S_];
__device__ float g_rowinv[BH_*S_];
__device__ float g_cmax[BH_*S_*NCHUNK];
__device__ float g_csum[BH_*S_*NCHUNK];
__device__ unsigned g_Vth[BH_*DEP_*(S_/2)];
__device__ unsigned g_Vtl[BH_*DEP_*(S_/2)];
__device__ float g_attn_scratch[ATTN_ELEMS];

__device__ __forceinline__ float neg_inf() { return __int_as_float(0xff800000); }

// ---- bf16 split helpers ----
__device__ __forceinline__ void split2(float x, float y, unsigned& h, unsigned& l) {
    __nv_bfloat162 hv = __floats2bfloat162_rn(x, y);
    float2 hf = __bfloat1622float2(hv);
    __nv_bfloat162 lv = __floats2bfloat162_rn(x - hf.x, y - hf.y);
    h = *(unsigned*)&hv;
    l = *(unsigned*)&lv;
}

__device__ __forceinline__ void mma16(float* c,
                                      unsigned a0, unsigned a1, unsigned a2, unsigned a3,
                                      unsigned b0, unsigned b1) {
    asm volatile(
        "mma.sync.aligned.m16n8k16.row.col.f32.bf16.bf16.f32 "
        "{%0,%1,%2,%3}, {%4,%5,%6,%7}, {%8,%9}, {%0,%1,%2,%3};\n"
        : "+f"(c[0]), "+f"(c[1]), "+f"(c[2]), "+f"(c[3])
        : "r"(a0), "r"(a1), "r"(a2), "r"(a3), "r"(b0), "r"(b1));
}

__device__ __forceinline__ void ldsm_x4(unsigned* r, const void* p) {
    unsigned addr = (unsigned)__cvta_generic_to_shared(p);
    asm volatile("ldmatrix.sync.aligned.m8n8.x4.shared.b16 {%0,%1,%2,%3}, [%4];"
        : "=r"(r[0]), "=r"(r[1]), "=r"(r[2]), "=r"(r[3]) : "r"(addr));
}

// ======================================================================
// Projection GEMM — unchanged from passing R9 kernel.
// ======================================================================
__global__ __launch_bounds__(256, 2)
void gemm_xwT_bf16(const float* __restrict__ X,
                   const float* __restrict__ W,
                   const float* __restrict__ bias,
                   float* __restrict__ C,
                   int K, int N, float alpha, int head_split)
{
    __shared__ unsigned Ah[128][20], Al[128][20];
    __shared__ unsigned Bh[64][20],  Bl[64][20];

    const int t = threadIdx.x, wid = t >> 5, lane = t & 31;
    const int gid = lane >> 2, tig = lane & 3;
    const int n0 = blockIdx.x * 64, m0 = blockIdx.y * 128;
    const int wm = (wid & 3) * 32, wn = (wid >> 2) * 32;

    const int a_r = lane & 15, a_c = ((lane >> 4) & 1) * 4;
    const int b_r = (lane & 7) + ((lane >> 4) & 1) * 8;
    const int b_c = ((lane >> 3) & 1) * 4;

    const int lr = t >> 1, lg = t & 1;
    const int br = t >> 2, bg = t & 3;

    const float* Xp = X + (size_t)(m0 + lr) * K + lg * 16;
    const float* Wp = W + (size_t)(n0 + br) * K + bg * 8;

    float acc[2][4][4];
#pragma unroll
    for (int i = 0; i < 2; i++)
#pragma unroll
        for (int j = 0; j < 4; j++)
#pragma unroll
            for (int q = 0; q < 4; q++) acc[i][j][q] = 0.0f;

    float4 xa[4], wb[2];
#pragma unroll
    for (int j = 0; j < 4; j++) xa[j] = *(const float4*)(Xp + j * 4);
#pragma unroll
    for (int j = 0; j < 2; j++) wb[j] = *(const float4*)(Wp + j * 4);

    for (int k0 = 0; k0 < K; k0 += 32) {
#pragma unroll
        for (int j = 0; j < 4; j++) {
            unsigned h, l;
            split2(xa[j].x, xa[j].y, h, l);
            Ah[lr][lg*8 + 2*j]     = h;  Al[lr][lg*8 + 2*j]     = l;
            split2(xa[j].z, xa[j].w, h, l);
            Ah[lr][lg*8 + 2*j + 1] = h;  Al[lr][lg*8 + 2*j + 1] = l;
        }
#pragma unroll
        for (int j = 0; j < 2; j++) {
            unsigned h, l;
            split2(wb[j].x, wb[j].y, h, l);
            Bh[br][bg*4 + 2*j]     = h;  Bl[br][bg*4 + 2*j]     = l;
            split2(wb[j].z, wb[j].w, h, l);
            Bh[br][bg*4 + 2*j + 1] = h;  Bl[br][bg*4 + 2*j + 1] = l;
        }
        __syncthreads();

        if (k0 + 32 < K) {
#pragma unroll
            for (int j = 0; j < 4; j++) xa[j] = *(const float4*)(Xp + k0 + 32 + j * 4);
#pragma unroll
            for (int j = 0; j < 2; j++) wb[j] = *(const float4*)(Wp + k0 + 32 + j * 4);
        }

#pragma unroll
        for (int step = 0; step < 2; step++) {
            const int kc = step * 8;
            unsigned ah[2][4], al[2][4], bhf[2][4], blf[2][4];
#pragma unroll
            for (int mt = 0; mt < 2; mt++) {
                ldsm_x4(ah[mt], &Ah[wm + mt*16 + a_r][kc + a_c]);
                ldsm_x4(al[mt], &Al[wm + mt*16 + a_r][kc + a_c]);
            }
#pragma unroll
            for (int np = 0; np < 2; np++) {
                ldsm_x4(bhf[np], &Bh[wn + np*16 + b_r][kc + b_c]);
                ldsm_x4(blf[np], &Bl[wn + np*16 + b_r][kc + b_c]);
            }
#pragma unroll
            for (int nt = 0; nt < 4; nt++) {
                const unsigned bh0 = bhf[nt>>1][(nt&1)*2], bh1 = bhf[nt>>1][(nt&1)*2+1];
                const unsigned bl0 = blf[nt>>1][(nt&1)*2], bl1 = blf[nt>>1][(nt&1)*2+1];
#pragma unroll
                for (int mt = 0; mt < 2; mt++) {
                    mma16(acc[mt][nt], ah[mt][0],ah[mt][1],ah[mt][2],ah[mt][3], bh0, bh1);
                    mma16(acc[mt][nt], ah[mt][0],ah[mt][1],ah[mt][2],ah[mt][3], bl0, bl1);
                    mma16(acc[mt][nt], al[mt][0],al[mt][1],al[mt][2],al[mt][3], bh0, bh1);
                }
            }
        }
        __syncthreads();
    }

#pragma unroll
    for (int mt = 0; mt < 2; mt++) {
#pragma unroll
        for (int nt = 0; nt < 4; nt++) {
            const int r0 = m0 + wm + mt*16 + gid;
            const int r1 = r0 + 8;
            const int c  = n0 + wn + nt*8 + tig*2;
            const float b0v = bias[c], b1v = bias[c+1];
            float2 v0, v1;
            v0.x = alpha * (acc[mt][nt][0] + b0v);
            v0.y = alpha * (acc[mt][nt][1] + b1v);
            v1.x = alpha * (acc[mt][nt][2] + b0v);
            v1.y = alpha * (acc[mt][nt][3] + b1v);
            if (head_split) {
                const int h = n0 / DEP_;
                const int dd = c - n0;
                const int b0_ = r0 / S_, s0 = r0 % S_;
                const int b1_ = r1 / S_, s1 = r1 % S_;
                *(float2*)(C + (((size_t)(b0_*H_ + h))*S_ + s0)*DEP_ + dd) = v0;
                *(float2*)(C + (((size_t)(b1_*H_ + h))*S_ + s1)*DEP_ + dd) = v1;
            } else {
                *(float2*)(C + (size_t)r0 * N + c) = v0;
                *(float2*)(C + (size_t)r1 * N + c) = v1;
            }
        }
    }
}

// ======================================================================
// logits v2: 128(m) x 256(n) strip per CTA; A fragments register-resident,
// reused over 4 n-tiles. Emits per-chunk online softmax partials.
// grid (8, 16, 24)
// ======================================================================
__global__ __launch_bounds__(256, 1)
void logits_bf16(const float* __restrict__ Qp,
                 const float* __restrict__ Kp,
                 const int*   __restrict__ mask,
                 float* __restrict__ attn,
                 float* __restrict__ cmax,
                 float* __restrict__ csum)
{
    __shared__ unsigned Sh[128][20], Sl[128][20];
    __shared__ int   smask[256];
    __shared__ float smx[2][128], ssm[2][128];

    const int t = threadIdx.x, wid = t >> 5, lane = t & 31;
    const int gid = lane >> 2, tig = lane & 3;
    const int nbase = blockIdx.x * 256, m0 = blockIdx.y * 128;
    const int bh = blockIdx.z, b = bh / H_;
    const int wm = (wid & 3) * 32, wn = (wid >> 2) * 32;
    const int hf = wid >> 2;

    const int a_r = lane & 15, a_c = ((lane >> 4) & 1) * 4;
    const int b_r = (lane & 7) + ((lane >> 4) & 1) * 8;
    const int b_c = ((lane >> 3) & 1) * 4;

    smask[t] = mask[b * S_ + nbase + t];

    const int lr = t >> 1, lg = t & 1;
    const int br = t >> 2, bg = t & 3;

    // ---------------- prologue: A (Q) -> register fragments, full K=64
    unsigned aH[2][4][4], aL[2][4][4];
#pragma unroll
    for (int ks = 0; ks < 2; ks++) {
        const float* Qb = Qp + ((size_t)bh * S_ + m0 + lr) * DEP_ + ks*32 + lg*16;
        float4 xa[4];
#pragma unroll
        for (int j = 0; j < 4; j++) xa[j] = *(const float4*)(Qb + j * 4);
#pragma unroll
        for (int j = 0; j < 4; j++) {
            unsigned h, l;
            split2(xa[j].x, xa[j].y, h, l);
            Sh[lr][lg*8 + 2*j]     = h;  Sl[lr][lg*8 + 2*j]     = l;
            split2(xa[j].z, xa[j].w, h, l);
            Sh[lr][lg*8 + 2*j + 1] = h;  Sl[lr][lg*8 + 2*j + 1] = l;
        }
        __syncthreads();
#pragma unroll
        for (int step = 0; step < 2; step++) {
            const int kc = step * 8;
#pragma unroll
            for (int mt = 0; mt < 2; mt++) {
                ldsm_x4(aH[mt][ks*2+step], &Sh[wm + mt*16 + a_r][kc + a_c]);
                ldsm_x4(aL[mt][ks*2+step], &Sl[wm + mt*16 + a_r][kc + a_c]);
            }
        }
        __syncthreads();
    }

    float runm[2][2], runs[2][2];
#pragma unroll
    for (int i = 0; i < 2; i++)
#pragma unroll
        for (int j = 0; j < 2; j++) { runm[i][j] = neg_inf(); runs[i][j] = 0.0f; }

    float acc[2][4][4];
    float* Cb = attn + (size_t)bh * S_ * S_;

    // B prefetch for it=0
    float4 wb[2];
    {
        const float* Kb = Kp + ((size_t)bh * S_ + nbase + br) * DEP_ + bg*8;
#pragma unroll
        for (int j = 0; j < 2; j++) wb[j] = *(const float4*)(Kb + j * 4);
    }

    // ---------------- main: 4 n-tiles x 2 k-slabs, flattened + unrolled
#pragma unroll
    for (int it = 0; it < 8; it++) {
        const int ni = it >> 1, ks = it & 1;
        if (ks == 0) {
#pragma unroll
            for (int i = 0; i < 2; i++)
#pragma unroll
                for (int j = 0; j < 4; j++)
#pragma unroll
                    for (int q = 0; q < 4; q++) acc[i][j][q] = 0.0f;
        }

        __syncthreads();   // previous ldsm done before overwrite
#pragma unroll
        for (int j = 0; j < 2; j++) {
            unsigned h, l;
            split2(wb[j].x, wb[j].y, h, l);
            Sh[br][bg*4 + 2*j]     = h;  Sl[br][bg*4 + 2*j]     = l;
            split2(wb[j].z, wb[j].w, h, l);
            Sh[br][bg*4 + 2*j + 1] = h;  Sl[br][bg*4 + 2*j + 1] = l;
        }
        __syncthreads();

        if (it + 1 < 8) {
            const int niN = (it+1) >> 1, ksN = (it+1) & 1;
            const float* Kb = Kp + ((size_t)bh * S_ + nbase + niN*64 + br) * DEP_
                              + ksN*32 + bg*8;
#pragma unroll
            for (int j = 0; j < 2; j++) wb[j] = *(const float4*)(Kb + j * 4);
        }

#pragma unroll
        for (int step = 0; step < 2; step++) {
            const int kc = step * 8;
            const int kchunk = ks*2 + step;
            unsigned bhf[2][4], blf[2][4];
#pragma unroll
            for (int np = 0; np < 2; np++) {
                ldsm_x4(bhf[np], &Sh[wn + np*16 + b_r][kc + b_c]);
                ldsm_x4(blf[np], &Sl[wn + np*16 + b_r][kc + b_c]);
            }
#pragma unroll
            for (int nt = 0; nt < 4; nt++) {
                const unsigned b0v = bhf[nt>>1][(nt&1)*2], b1v = bhf[nt>>1][(nt&1)*2+1];
                const unsigned c0v = blf[nt>>1][(nt&1)*2], c1v = blf[nt>>1][(nt&1)*2+1];
#pragma unroll
                for (int mt = 0; mt < 2; mt++) {
                    mma16(acc[mt][nt], aH[mt][kchunk][0],aH[mt][kchunk][1],
                                       aH[mt][kchunk][2],aH[mt][kchunk][3], b0v, b1v);
                    mma16(acc[mt][nt], aH[mt][kchunk][0],aH[mt][kchunk][1],
                                       aH[mt][kchunk][2],aH[mt][kchunk][3], c0v, c1v);
                    mma16(acc[mt][nt], aL[mt][kchunk][0],aL[mt][kchunk][1],
                                       aL[mt][kchunk][2],aL[mt][kchunk][3], b0v, b1v);
                }
            }
        }

        if (ks == 1) {
            // -------- epilogue for n-tile ni: mask, store, online stats
            bool mz[4][2];
#pragma unroll
            for (int nt = 0; nt < 4; nt++) {
                const int lc = ni*64 + wn + nt*8 + tig*2;
                mz[nt][0] = (smask[lc] == 0);
                mz[nt][1] = (smask[lc+1] == 0);
            }
#pragma unroll
            for (int mt = 0; mt < 2; mt++) {
#pragma unroll
                for (int nt = 0; nt < 4; nt++) {
                    const int r0 = m0 + wm + mt*16 + gid;
                    const int r1 = r0 + 8;
                    const int c  = nbase + ni*64 + wn + nt*8 + tig*2;
                    float2 v0, v1;
                    v0.x = mz[nt][0] ? neg_inf() : acc[mt][nt][0];
                    v0.y = mz[nt][1] ? neg_inf() : acc[mt][nt][1];
                    v1.x = mz[nt][0] ? neg_inf() : acc[mt][nt][2];
                    v1.y = mz[nt][1] ? neg_inf() : acc[mt][nt][3];
                    *(float2*)(Cb + (size_t)r0 * S_ + c) = v0;
                    *(float2*)(Cb + (size_t)r1 * S_ + c) = v1;
                }
            }
#pragma unroll
            for (int mt = 0; mt < 2; mt++) {
#pragma unroll
                for (int rh = 0; rh < 2; rh++) {
                    float mx = neg_inf();
#pragma unroll
                    for (int nt = 0; nt < 4; nt++) {
                        float v0 = mz[nt][0] ? neg_inf() : acc[mt][nt][rh*2];
                        float v1 = mz[nt][1] ? neg_inf() : acc[mt][nt][rh*2+1];
                        mx = fmaxf(mx, fmaxf(v0, v1));
                    }
                    mx = fmaxf(mx, __shfl_xor_sync(0xffffffffu, mx, 1));
                    mx = fmaxf(mx, __shfl_xor_sync(0xffffffffu, mx, 2));
                    float s = 0.0f;
                    if (mx != neg_inf()) {
#pragma unroll
                        for (int nt = 0; nt < 4; nt++) {
                            if (!mz[nt][0]) s += __expf(acc[mt][nt][rh*2]   - mx);
                            if (!mz[nt][1]) s += __expf(acc[mt][nt][rh*2+1] - mx);
                        }
                    }
                    s += __shfl_xor_sync(0xffffffffu, s, 1);
                    s += __shfl_xor_sync(0xffffffffu, s, 2);
                    if (mx > runm[mt][rh]) {
                        runs[mt][rh] = runs[mt][rh] * __expf(runm[mt][rh] - mx) + s;
                        runm[mt][rh] = mx;
                    } else if (mx != neg_inf()) {
                        runs[mt][rh] += s * __expf(mx - runm[mt][rh]);
                    }
                }
            }
        }
    }

    // ---------------- cross-half combine + write chunk partials
    __syncthreads();
    if (tig == 0) {
#pragma unroll
        for (int mt = 0; mt < 2; mt++)
#pragma unroll
            for (int rh = 0; rh < 2; rh++) {
                const int row = wm + mt*16 + rh*8 + gid;
                smx[hf][row] = runm[mt][rh];
                ssm[hf][row] = runs[mt][rh];
            }
    }
    __syncthreads();
    if (t < 128) {
        const float m0v = smx[0][t], m1v = smx[1][t];
        const float s0 = ssm[0][t], s1 = ssm[1][t];
        const float M = fmaxf(m0v, m1v);
        float S = 0.0f;
        if (m0v != neg_inf()) S += s0 * __expf(m0v - M);
        if (m1v != neg_inf()) S += s1 * __expf(m1v - M);
        const size_t row = (size_t)bh * S_ + m0 + t;
        cmax[row * NCHUNK + blockIdx.x] = M;
        csum[row * NCHUNK + blockIdx.x] = S;
    }
}

// ======================================================================
// combine NCHUNK partials per row -> rowmax, rowinv
// ======================================================================
__global__ __launch_bounds__(256)
void chunk_reduce(const float* __restrict__ cmax,
                  const float* __restrict__ csum,
                  float* __restrict__ gmax,
                  float* __restrict__ ginv)
{
    const int r = blockIdx.x * 256 + threadIdx.x;
    if (r >= BH_ * S_) return;
    float M = neg_inf(), S = 0.0f;
#pragma unroll
    for (int c = 0; c < NCHUNK; c++) {
        const float m = cmax[(size_t)r * NCHUNK + c];
        const float s = csum[(size_t)r * NCHUNK + c];
        if (m > M) { S = S * __expf(M - m) + s; M = m; }
        else if (m != neg_inf()) { S += s * __expf(m - M); }
    }
    gmax[r] = M;
    ginv[r] = 1.0f / S;
}

// ======================================================================
// vsplit: V [bh, n, d] fp32 -> k-major split bf16 pairs
// Vth/Vtl [bh, d(64), npair(1024)]. grid (S/32, BH), block 256.
// ======================================================================
__global__ __launch_bounds__(256)
void vsplit_kernel(const float* __restrict__ Vp,
                   unsigned* __restrict__ Vth,
                   unsigned* __restrict__ Vtl)
{
    __shared__ float tile[32][65];
    const int t = threadIdx.x;
    const int n0 = blockIdx.x * 32;
    const int bh = blockIdx.y;

#pragma unroll
    for (int i = 0; i < 8; i++) {
        const int idx = t + i * 256;
        const int r = idx >> 6, c = idx & 63;
        tile[r][c] = Vp[((size_t)bh * S_ + n0 + r) * DEP_ + c];
    }
    __syncthreads();

#pragma unroll
    for (int i = 0; i < 4; i++) {
        const int idx = t * 4 + i;
        const int d = idx >> 4, np = idx & 15;
        unsigned h, l;
        split2(tile[2*np][d], tile[2*np + 1][d], h, l);
        const size_t o = ((size_t)bh * DEP_ + d) * (S_/2) + n0/2 + np;
        Vth[o] = h;
        Vtl[o] = l;
    }
}

// ======================================================================
// ctx = softmax(logits) @ V, normalizing attn in place.
// V comes pre-split/transposed from Vth/Vtl. grid (16, 24)
// ======================================================================
__global__ __launch_bounds__(256, 2)
void ctx_bf16(float* __restrict__ attn,
              const unsigned* __restrict__ Vth,
              const unsigned* __restrict__ Vtl,
              const float* __restrict__ gmax,
              const float* __restrict__ ginv,
              float* __restrict__ ctx)
{
    __shared__ unsigned Ah[128][20], Al[128][20];
    __shared__ unsigned Vh[64][20], Vl[64][20];

    const int t = threadIdx.x, wid = t >> 5, lane = t & 31;
    const int gid = lane >> 2, tig = lane & 3;
    const int m0 = blockIdx.x * 128;
    const int bh = blockIdx.y;
    const int b  = bh / H_, h = bh % H_;
    const int wm = (wid & 3) * 32, wd = (wid >> 2) * 32;

    const int a_r = lane & 15, a_c = ((lane >> 4) & 1) * 4;
    const int b_r = (lane & 7) + ((lane >> 4) & 1) * 8;
    const int b_c = ((lane >> 3) & 1) * 4;

    const int lr = t >> 1, lg = t & 1;
    const int vr = t >> 2, vg = t & 3;

    float* Ap = attn + ((size_t)bh * S_ + m0 + lr) * S_ + lg * 16;
    const unsigned* VthB = Vth + ((size_t)bh * DEP_ + vr) * (S_/2) + vg * 4;
    const unsigned* VtlB = Vtl + ((size_t)bh * DEP_ + vr) * (S_/2) + vg * 4;

    const float mr = gmax[bh * S_ + m0 + lr];
    const float ir = ginv[bh * S_ + m0 + lr];

    float acc[2][4][4];
#pragma unroll
    for (int i = 0; i < 2; i++)
#pragma unroll
        for (int j = 0; j < 4; j++)
#pragma unroll
            for (int q = 0; q < 4; q++) acc[i][j][q] = 0.0f;

    float4 av[4];
#pragma unroll
    for (int j = 0; j < 4; j++) av[j] = *(const float4*)(Ap + j * 4);
    uint4 vh4 = *(const uint4*)(VthB);
    uint4 vl4 = *(const uint4*)(VtlB);

    for (int nc = 0; nc < S_; nc += 32) {
#pragma unroll
        for (int j = 0; j < 4; j++) {
            float4 pv;
            pv.x = __expf(av[j].x - mr) * ir;
            pv.y = __expf(av[j].y - mr) * ir;
            pv.z = __expf(av[j].z - mr) * ir;
            pv.w = __expf(av[j].w - mr) * ir;
            *(float4*)(Ap + nc + j * 4) = pv;   // final normalized attn
            unsigned hh, ll;
            split2(pv.x, pv.y, hh, ll);
            Ah[lr][lg*8 + 2*j]     = hh;  Al[lr][lg*8 + 2*j]     = ll;
            split2(pv.z, pv.w, hh, ll);
            Ah[lr][lg*8 + 2*j + 1] = hh;  Al[lr][lg*8 + 2*j + 1] = ll;
        }
        *(uint4*)&Vh[vr][vg*4] = vh4;
        *(uint4*)&Vl[vr][vg*4] = vl4;
        __syncthreads();

        if (nc + 32 < S_) {
#pragma unroll
            for (int j = 0; j < 4; j++) av[j] = *(const float4*)(Ap + nc + 32 + j * 4);
            vh4 = *(const uint4*)(VthB + (nc + 32)/2);
            vl4 = *(const uint4*)(VtlB + (nc + 32)/2);
        }

#pragma unroll
        for (int step = 0; step < 2; step++) {
            const int kc = step * 8;
            unsigned ah[2][4], al[2][4], bhf[2][4], blf[2][4];
#pragma unroll
            for (int mt = 0; mt < 2; mt++) {
                ldsm_x4(ah[mt], &Ah[wm + mt*16 + a_r][kc + a_c]);
                ldsm_x4(al[mt], &Al[wm + mt*16 + a_r][kc + a_c]);
            }
#pragma unroll
            for (int np = 0; np < 2; np++) {
                ldsm_x4(bhf[np], &Vh[wd + np*16 + b_r][kc + b_c]);
                ldsm_x4(blf[np], &Vl[wd + np*16 + b_r][kc + b_c]);
            }
#pragma unroll
            for (int dt = 0; dt < 4; dt++) {
                const unsigned bh0 = bhf[dt>>1][(dt&1)*2], bh1 = bhf[dt>>1][(dt&1)*2+1];
                const unsigned bl0 = blf[dt>>1][(dt&1)*2], bl1 = blf[dt>>1][(dt&1)*2+1];
#pragma unroll
                for (int mt = 0; mt < 2; mt++) {
                    mma16(acc[mt][dt], ah[mt][0],ah[mt][1],ah[mt][2],ah[mt][3], bh0, bh1);
                    mma16(acc[mt][dt], ah[mt][0],ah[mt][1],ah[mt][2],ah[mt][3], bl0, bl1);
                    mma16(acc[mt][dt], al[mt][0],al[mt][1],al[mt][2],al[mt][3], bh0, bh1);
                }
            }
        }
        __syncthreads();
    }

#pragma unroll
    for (int mt = 0; mt < 2; mt++) {
#pragma unroll
        for (int dt = 0; dt < 4; dt++) {
            const int r0 = m0 + wm + mt*16 + gid;
            const int r1 = r0 + 8;
            const int d  = wd + dt*8 + tig*2;
            float2 v0 = {acc[mt][dt][0], acc[mt][dt][1]};
            float2 v1 = {acc[mt][dt][2], acc[mt][dt][3]};
            *(float2*)(ctx + ((size_t)b * S_ + r0) * D_ + h * DEP_ + d) = v0;
            *(float2*)(ctx + ((size_t)b * S_ + r1) * D_ + h * DEP_ + d) = v1;
        }
    }
}

// ======================================================================
extern "C" void kernel_launch(void* const* d_in, const int* in_sizes, int n_in,
                              void* d_out, int out_size)
{
    const float* q    = (const float*)d_in[0];
    const float* k    = (const float*)d_in[1];
    const float* v    = (const float*)d_in[2];
    const int*   mask = (const int*)  d_in[3];
    const float* wq_w = (const float*)d_in[4];
    const float* wq_b = (const float*)d_in[5];
    const float* wk_w = (const float*)d_in[6];
    const float* wk_b = (const float*)d_in[7];
    const float* wv_w = (const float*)d_in[8];
    const float* wv_b = (const float*)d_in[9];
    const float* wo_w = (const float*)d_in[10];
    const float* wo_b = (const float*)d_in[11];
    float* out = (float*)d_out;

    float *Qp, *Kp, *Vp, *ctxp, *rmax, *rinv, *cmax, *csum, *attn_s;
    unsigned *Vth, *Vtl;
    cudaGetSymbolAddress((void**)&Qp,     g_Qp);
    cudaGetSymbolAddress((void**)&Kp,     g_Kp);
    cudaGetSymbolAddress((void**)&Vp,     g_Vp);
    cudaGetSymbolAddress((void**)&ctxp,   g_ctx);
    cudaGetSymbolAddress((void**)&rmax,   g_rowmax);
    cudaGetSymbolAddress((void**)&rinv,   g_rowinv);
    cudaGetSymbolAddress((void**)&cmax,   g_cmax);
    cudaGetSymbolAddress((void**)&csum,   g_csum);
    cudaGetSymbolAddress((void**)&Vth,    g_Vth);
    cudaGetSymbolAddress((void**)&Vtl,    g_Vtl);
    cudaGetSymbolAddress((void**)&attn_s, g_attn_scratch);

    const long long need = (long long)OUT_ELEMS + (long long)ATTN_ELEMS;
    float* attn = ((long long)out_size >= need) ? (out + OUT_ELEMS) : attn_s;

    // Q/K/V projections (Q pre-scaled by 1/sqrt(64) = 0.125)
    dim3 pgrid(D_/64, MROWS/128);
    gemm_xwT_bf16<<<pgrid, 256>>>(q, wq_w, wq_b, Qp, D_, D_, 0.125f, 1);
    gemm_xwT_bf16<<<pgrid, 256>>>(k, wk_w, wk_b, Kp, D_, D_, 1.0f, 1);
    gemm_xwT_bf16<<<pgrid, 256>>>(v, wv_w, wv_b, Vp, D_, D_, 1.0f, 1);

    // pre-split/transpose V for the AV GEMM
    vsplit_kernel<<<dim3(S_/32, BH_), 256>>>(Vp, Vth, Vtl);

    // raw masked logits + per-chunk softmax partials
    logits_bf16<<<dim3(S_/256, S_/128, BH_), 256>>>(Qp, Kp, mask, attn, cmax, csum);

    // combine partials -> row stats
    chunk_reduce<<<dim3((BH_*S_ + 255)/256), 256>>>(cmax, csum, rmax, rinv);

    // ctx = softmax @ V; normalizes attn in place as it goes
    ctx_bf16<<<dim3(S_/128, BH_), 256>>>(attn, Vth, Vtl, rmax, rinv, ctxp);

    // output projection
    gemm_xwT_bf16<<<pgrid, 256>>>(ctxp, wo_w, wo_b, out, D_, D_, 1.0f, 0);
}

// round 12
// speedup vs baseline: 2.7621x; 1.2097x over previous
#include <cuda_runtime.h>
#include <cuda_bf16.h>
#include <math.h>

#define B_    2
#define S_    2048
#define D_    768
#define H_    12
#define DEP_  64
#define BH_   (B_*H_)            // 24
#define MROWS (B_*S_)            // 4096
#define OUT_ELEMS (B_*S_*D_)     // 3145728
#define ATTN_ELEMS (BH_*S_*S_)   // 100663296
#define NCHUNK 8

#define DYN_SMEM_BYTES 61440     // 15360 words, all three mma kernels

// ---- scratch (alloc-free, __device__ globals) ----
__device__ float g_Qp[BH_*S_*DEP_];
__device__ float g_Kp[BH_*S_*DEP_];
__device__ float g_Vp[BH_*S_*DEP_];
__device__ float g_ctx[MROWS*D_];
__device__ float g_rowmax[BH_*S_];
__device__ float g_rowinv[BH_*S_];
__device__ float g_cmax[BH_*S_*NCHUNK];
__device__ float g_csum[BH_*S_*NCHUNK];
__device__ unsigned g_Vth[BH_*DEP_*(S_/2)];
__device__ unsigned g_Vtl[BH_*DEP_*(S_/2)];
__device__ float g_attn_scratch[ATTN_ELEMS];

__device__ __forceinline__ float neg_inf() { return __int_as_float(0xff800000); }

__device__ __forceinline__ void split2(float x, float y, unsigned& h, unsigned& l) {
    __nv_bfloat162 hv = __floats2bfloat162_rn(x, y);
    float2 hf = __bfloat1622float2(hv);
    __nv_bfloat162 lv = __floats2bfloat162_rn(x - hf.x, y - hf.y);
    h = *(unsigned*)&hv;
    l = *(unsigned*)&lv;
}

__device__ __forceinline__ void mma16(float* c,
                                      unsigned a0, unsigned a1, unsigned a2, unsigned a3,
                                      unsigned b0, unsigned b1) {
    asm volatile(
        "mma.sync.aligned.m16n8k16.row.col.f32.bf16.bf16.f32 "
        "{%0,%1,%2,%3}, {%4,%5,%6,%7}, {%8,%9}, {%0,%1,%2,%3};\n"
        : "+f"(c[0]), "+f"(c[1]), "+f"(c[2]), "+f"(c[3])
        : "r"(a0), "r"(a1), "r"(a2), "r"(a3), "r"(b0), "r"(b1));
}

__device__ __forceinline__ void ldsm_x4(unsigned* r, const void* p) {
    unsigned addr = (unsigned)__cvta_generic_to_shared(p);
    asm volatile("ldmatrix.sync.aligned.m8n8.x4.shared.b16 {%0,%1,%2,%3}, [%4];"
        : "=r"(r[0]), "=r"(r[1]), "=r"(r[2]), "=r"(r[3]) : "r"(addr));
}

// ======================================================================
// Projection GEMM v2: C = alpha*(X @ W^T + bias); 128m x 64n tile,
// k-slab 32, double-buffered smem stages, ONE sync per slab.
// dyn smem layout (words), stage st in {0,1}, base = st*7680:
//   AH @ base, AL @ base+2560, BH @ base+5120, BL @ base+6400
// ======================================================================
__global__ __launch_bounds__(256, 2)
void gemm_xwT_bf16(const float* __restrict__ X,
                   const float* __restrict__ W,
                   const float* __restrict__ bias,
                   float* __restrict__ C,
                   int K, int N, float alpha, int head_split)
{
    extern __shared__ unsigned dsm[];

    const int t = threadIdx.x, wid = t >> 5, lane = t & 31;
    const int gid = lane >> 2, tig = lane & 3;
    const int n0 = blockIdx.x * 64, m0 = blockIdx.y * 128;
    const int wm = (wid & 3) * 32, wn = (wid >> 2) * 32;

    const int a_r = lane & 15, a_c = ((lane >> 4) & 1) * 4;
    const int b_r = (lane & 7) + ((lane >> 4) & 1) * 8;
    const int b_c = ((lane >> 3) & 1) * 4;

    const int lr = t >> 1, lg = t & 1;   // A: row, half(16 floats)
    const int br = t >> 2, bg = t & 3;   // B: row, quarter(8 floats)

    const float* Xp = X + (size_t)(m0 + lr) * K + lg * 16;
    const float* Wp = W + (size_t)(n0 + br) * K + bg * 8;

    float acc[2][4][4];
#pragma unroll
    for (int i = 0; i < 2; i++)
#pragma unroll
        for (int j = 0; j < 4; j++)
#pragma unroll
            for (int q = 0; q < 4; q++) acc[i][j][q] = 0.0f;

    const int NS = K / 32;

    float4 xa[4], wb[2];
#pragma unroll
    for (int j = 0; j < 4; j++) xa[j] = *(const float4*)(Xp + j * 4);
#pragma unroll
    for (int j = 0; j < 2; j++) wb[j] = *(const float4*)(Wp + j * 4);

    // store slab 0 -> stage 0
    {
        unsigned* AH = dsm;            unsigned* AL = dsm + 2560;
        unsigned* BH = dsm + 5120;     unsigned* BL = dsm + 6400;
#pragma unroll
        for (int j = 0; j < 4; j++) {
            unsigned h, l;
            split2(xa[j].x, xa[j].y, h, l);
            AH[lr*20 + lg*8 + 2*j]   = h;  AL[lr*20 + lg*8 + 2*j]   = l;
            split2(xa[j].z, xa[j].w, h, l);
            AH[lr*20 + lg*8 + 2*j+1] = h;  AL[lr*20 + lg*8 + 2*j+1] = l;
        }
#pragma unroll
        for (int j = 0; j < 2; j++) {
            unsigned h, l;
            split2(wb[j].x, wb[j].y, h, l);
            BH[br*20 + bg*4 + 2*j]   = h;  BL[br*20 + bg*4 + 2*j]   = l;
            split2(wb[j].z, wb[j].w, h, l);
            BH[br*20 + bg*4 + 2*j+1] = h;  BL[br*20 + bg*4 + 2*j+1] = l;
        }
    }
    __syncthreads();

#pragma unroll 1
    for (int s = 0; s < NS; s++) {
        const int st = s & 1;
        const unsigned base = st * 7680;

        if (s + 1 < NS) {
            const int k0 = (s + 1) * 32;
#pragma unroll
            for (int j = 0; j < 4; j++) xa[j] = *(const float4*)(Xp + k0 + j * 4);
#pragma unroll
            for (int j = 0; j < 2; j++) wb[j] = *(const float4*)(Wp + k0 + j * 4);
        }

        // mma from stage st
#pragma unroll
        for (int step = 0; step < 2; step++) {
            const int kc = step * 8;
            unsigned ah[2][4], al[2][4], bhf[2][4], blf[2][4];
#pragma unroll
            for (int mt = 0; mt < 2; mt++) {
                ldsm_x4(ah[mt], dsm + base + (wm + mt*16 + a_r)*20 + kc + a_c);
                ldsm_x4(al[mt], dsm + base + 2560 + (wm + mt*16 + a_r)*20 + kc + a_c);
            }
#pragma unroll
            for (int np = 0; np < 2; np++) {
                ldsm_x4(bhf[np], dsm + base + 5120 + (wn + np*16 + b_r)*20 + kc + b_c);
                ldsm_x4(blf[np], dsm + base + 6400 + (wn + np*16 + b_r)*20 + kc + b_c);
            }
#pragma unroll
            for (int nt = 0; nt < 4; nt++) {
                const unsigned bh0 = bhf[nt>>1][(nt&1)*2], bh1 = bhf[nt>>1][(nt&1)*2+1];
                const unsigned bl0 = blf[nt>>1][(nt&1)*2], bl1 = blf[nt>>1][(nt&1)*2+1];
#pragma unroll
                for (int mt = 0; mt < 2; mt++) {
                    mma16(acc[mt][nt], ah[mt][0],ah[mt][1],ah[mt][2],ah[mt][3], bh0, bh1);
                    mma16(acc[mt][nt], ah[mt][0],ah[mt][1],ah[mt][2],ah[mt][3], bl0, bl1);
                    mma16(acc[mt][nt], al[mt][0],al[mt][1],al[mt][2],al[mt][3], bh0, bh1);
                }
            }
        }

        // store slab s+1 -> stage st^1
        if (s + 1 < NS) {
            const unsigned nb = (st ^ 1) * 7680;
            unsigned* AH = dsm + nb;          unsigned* AL = dsm + nb + 2560;
            unsigned* BH = dsm + nb + 5120;   unsigned* BL = dsm + nb + 6400;
#pragma unroll
            for (int j = 0; j < 4; j++) {
                unsigned h, l;
                split2(xa[j].x, xa[j].y, h, l);
                AH[lr*20 + lg*8 + 2*j]   = h;  AL[lr*20 + lg*8 + 2*j]   = l;
                split2(xa[j].z, xa[j].w, h, l);
                AH[lr*20 + lg*8 + 2*j+1] = h;  AL[lr*20 + lg*8 + 2*j+1] = l;
            }
#pragma unroll
            for (int j = 0; j < 2; j++) {
                unsigned h, l;
                split2(wb[j].x, wb[j].y, h, l);
                BH[br*20 + bg*4 + 2*j]   = h;  BL[br*20 + bg*4 + 2*j]   = l;
                split2(wb[j].z, wb[j].w, h, l);
                BH[br*20 + bg*4 + 2*j+1] = h;  BL[br*20 + bg*4 + 2*j+1] = l;
            }
        }
        __syncthreads();
    }

#pragma unroll
    for (int mt = 0; mt < 2; mt++) {
#pragma unroll
        for (int nt = 0; nt < 4; nt++) {
            const int r0 = m0 + wm + mt*16 + gid;
            const int r1 = r0 + 8;
            const int c  = n0 + wn + nt*8 + tig*2;
            const float b0v = bias[c], b1v = bias[c+1];
            float2 v0, v1;
            v0.x = alpha * (acc[mt][nt][0] + b0v);
            v0.y = alpha * (acc[mt][nt][1] + b1v);
            v1.x = alpha * (acc[mt][nt][2] + b0v);
            v1.y = alpha * (acc[mt][nt][3] + b1v);
            if (head_split) {
                const int h = n0 / DEP_;
                const int dd = c - n0;
                const int b0_ = r0 / S_, s0 = r0 % S_;
                const int b1_ = r1 / S_, s1 = r1 % S_;
                *(float2*)(C + (((size_t)(b0_*H_ + h))*S_ + s0)*DEP_ + dd) = v0;
                *(float2*)(C + (((size_t)(b1_*H_ + h))*S_ + s1)*DEP_ + dd) = v1;
            } else {
                *(float2*)(C + (size_t)r0 * N + c) = v0;
                *(float2*)(C + (size_t)r1 * N + c) = v1;
            }
        }
    }
}

// ======================================================================
// logits v3: 128m x 256n strip; A(Q) smem-resident (both k-slabs),
// B double-buffered, ONE sync per iteration; fused online stats.
// dyn smem layout (words): AH slab s @ s*2560, AL @ 5120 + s*2560,
//   B stage st: BH @ 10240 + st*2560, BL @ +1280. total 15360 words.
// grid (8, 16, 24)
// ======================================================================
__global__ __launch_bounds__(256, 2)
void logits_bf16(const float* __restrict__ Qp,
                 const float* __restrict__ Kp,
                 const int*   __restrict__ mask,
                 float* __restrict__ attn,
                 float* __restrict__ cmax,
                 float* __restrict__ csum)
{
    extern __shared__ unsigned dsm[];
    __shared__ int   smask[256];
    __shared__ float smx[2][128], ssm[2][128];

    const int t = threadIdx.x, wid = t >> 5, lane = t & 31;
    const int gid = lane >> 2, tig = lane & 3;
    const int nbase = blockIdx.x * 256, m0 = blockIdx.y * 128;
    const int bh = blockIdx.z, b = bh / H_;
    const int wm = (wid & 3) * 32, wn = (wid >> 2) * 32;
    const int hf = wid >> 2;

    const int a_r = lane & 15, a_c = ((lane >> 4) & 1) * 4;
    const int b_r = (lane & 7) + ((lane >> 4) & 1) * 8;
    const int b_c = ((lane >> 3) & 1) * 4;

    smask[t] = mask[b * S_ + nbase + t];

    const int br = t >> 2, bg = t & 3;

    // ---- A: load full K=64 into smem (slab = t&1, row = t>>1)
    {
        const int slab = t & 1, row = t >> 1;
        const float* Qb = Qp + ((size_t)bh * S_ + m0 + row) * DEP_ + slab * 32;
        unsigned* AH = dsm + slab * 2560;
        unsigned* AL = dsm + 5120 + slab * 2560;
#pragma unroll
        for (int g = 0; g < 4; g++) {
            float4 f0 = *(const float4*)(Qb + g * 8);
            float4 f1 = *(const float4*)(Qb + g * 8 + 4);
            unsigned h, l;
            split2(f0.x, f0.y, h, l);
            AH[row*20 + g*4 + 0] = h;  AL[row*20 + g*4 + 0] = l;
            split2(f0.z, f0.w, h, l);
            AH[row*20 + g*4 + 1] = h;  AL[row*20 + g*4 + 1] = l;
            split2(f1.x, f1.y, h, l);
            AH[row*20 + g*4 + 2] = h;  AL[row*20 + g*4 + 2] = l;
            split2(f1.z, f1.w, h, l);
            AH[row*20 + g*4 + 3] = h;  AL[row*20 + g*4 + 3] = l;
        }
    }

    // ---- B it=0 load + store into stage 0
    float4 wb[2];
    {
        const float* Kb = Kp + ((size_t)bh * S_ + nbase + br) * DEP_ + bg * 8;
#pragma unroll
        for (int j = 0; j < 2; j++) wb[j] = *(const float4*)(Kb + j * 4);
        unsigned* BH = dsm + 10240;
        unsigned* BL = dsm + 10240 + 1280;
#pragma unroll
        for (int j = 0; j < 2; j++) {
            unsigned h, l;
            split2(wb[j].x, wb[j].y, h, l);
            BH[br*20 + bg*4 + 2*j]   = h;  BL[br*20 + bg*4 + 2*j]   = l;
            split2(wb[j].z, wb[j].w, h, l);
            BH[br*20 + bg*4 + 2*j+1] = h;  BL[br*20 + bg*4 + 2*j+1] = l;
        }
    }
    __syncthreads();

    float runm[2][2], runs[2][2];
#pragma unroll
    for (int i = 0; i < 2; i++)
#pragma unroll
        for (int j = 0; j < 2; j++) { runm[i][j] = neg_inf(); runs[i][j] = 0.0f; }

    float acc[2][4][4];
    float* Cb = attn + (size_t)bh * S_ * S_;

#pragma unroll
    for (int it = 0; it < 8; it++) {
        const int ni = it >> 1, ks = it & 1, st = it & 1;
        if (ks == 0) {
#pragma unroll
            for (int i = 0; i < 2; i++)
#pragma unroll
                for (int j = 0; j < 4; j++)
#pragma unroll
                    for (int q = 0; q < 4; q++) acc[i][j][q] = 0.0f;
        }

        if (it + 1 < 8) {
            const int niN = (it+1) >> 1, ksN = (it+1) & 1;
            const float* Kb = Kp + ((size_t)bh * S_ + nbase + niN*64 + br) * DEP_
                              + ksN*32 + bg*8;
#pragma unroll
            for (int j = 0; j < 2; j++) wb[j] = *(const float4*)(Kb + j * 4);
        }

        // ---- mma: A slab ks, B stage st
#pragma unroll
        for (int step = 0; step < 2; step++) {
            const int kc = step * 8;
            unsigned ah[2][4], al[2][4], bhf[2][4], blf[2][4];
#pragma unroll
            for (int mt = 0; mt < 2; mt++) {
                ldsm_x4(ah[mt], dsm + ks*2560        + (wm + mt*16 + a_r)*20 + kc + a_c);
                ldsm_x4(al[mt], dsm + 5120 + ks*2560 + (wm + mt*16 + a_r)*20 + kc + a_c);
            }
#pragma unroll
            for (int np = 0; np < 2; np++) {
                ldsm_x4(bhf[np], dsm + 10240 + st*2560        + (wn + np*16 + b_r)*20 + kc + b_c);
                ldsm_x4(blf[np], dsm + 10240 + st*2560 + 1280 + (wn + np*16 + b_r)*20 + kc + b_c);
            }
#pragma unroll
            for (int nt = 0; nt < 4; nt++) {
                const unsigned b0v = bhf[nt>>1][(nt&1)*2], b1v = bhf[nt>>1][(nt&1)*2+1];
                const unsigned c0v = blf[nt>>1][(nt&1)*2], c1v = blf[nt>>1][(nt&1)*2+1];
#pragma unroll
                for (int mt = 0; mt < 2; mt++) {
                    mma16(acc[mt][nt], ah[mt][0],ah[mt][1],ah[mt][2],ah[mt][3], b0v, b1v);
                    mma16(acc[mt][nt], ah[mt][0],ah[mt][1],ah[mt][2],ah[mt][3], c0v, c1v);
                    mma16(acc[mt][nt], al[mt][0],al[mt][1],al[mt][2],al[mt][3], b0v, b1v);
                }
            }
        }

        if (ks == 1) {
            // -------- epilogue for n-tile ni
            bool mz[4][2];
#pragma unroll
            for (int nt = 0; nt < 4; nt++) {
                const int lc = ni*64 + wn + nt*8 + tig*2;
                mz[nt][0] = (smask[lc] == 0);
                mz[nt][1] = (smask[lc+1] == 0);
            }
#pragma unroll
            for (int mt = 0; mt < 2; mt++) {
#pragma unroll
                for (int nt = 0; nt < 4; nt++) {
                    const int r0 = m0 + wm + mt*16 + gid;
                    const int r1 = r0 + 8;
                    const int c  = nbase + ni*64 + wn + nt*8 + tig*2;
                    float2 v0, v1;
                    v0.x = mz[nt][0] ? neg_inf() : acc[mt][nt][0];
                    v0.y = mz[nt][1] ? neg_inf() : acc[mt][nt][1];
                    v1.x = mz[nt][0] ? neg_inf() : acc[mt][nt][2];
                    v1.y = mz[nt][1] ? neg_inf() : acc[mt][nt][3];
                    *(float2*)(Cb + (size_t)r0 * S_ + c) = v0;
                    *(float2*)(Cb + (size_t)r1 * S_ + c) = v1;
                }
            }
#pragma unroll
            for (int mt = 0; mt < 2; mt++) {
#pragma unroll
                for (int rh = 0; rh < 2; rh++) {
                    float mx = neg_inf();
#pragma unroll
                    for (int nt = 0; nt < 4; nt++) {
                        float v0 = mz[nt][0] ? neg_inf() : acc[mt][nt][rh*2];
                        float v1 = mz[nt][1] ? neg_inf() : acc[mt][nt][rh*2+1];
                        mx = fmaxf(mx, fmaxf(v0, v1));
                    }
                    mx = fmaxf(mx, __shfl_xor_sync(0xffffffffu, mx, 1));
                    mx = fmaxf(mx, __shfl_xor_sync(0xffffffffu, mx, 2));
                    float s = 0.0f;
                    if (mx != neg_inf()) {
#pragma unroll
                        for (int nt = 0; nt < 4; nt++) {
                            if (!mz[nt][0]) s += __expf(acc[mt][nt][rh*2]   - mx);
                            if (!mz[nt][1]) s += __expf(acc[mt][nt][rh*2+1] - mx);
                        }
                    }
                    s += __shfl_xor_sync(0xffffffffu, s, 1);
                    s += __shfl_xor_sync(0xffffffffu, s, 2);
                    if (mx > runm[mt][rh]) {
                        runs[mt][rh] = runs[mt][rh] * __expf(runm[mt][rh] - mx) + s;
                        runm[mt][rh] = mx;
                    } else if (mx != neg_inf()) {
                        runs[mt][rh] += s * __expf(mx - runm[mt][rh]);
                    }
                }
            }
        }

        // ---- store B it+1 into stage st^1
        if (it + 1 < 8) {
            unsigned* BH = dsm + 10240 + (st^1)*2560;
            unsigned* BL = BH + 1280;
#pragma unroll
            for (int j = 0; j < 2; j++) {
                unsigned h, l;
                split2(wb[j].x, wb[j].y, h, l);
                BH[br*20 + bg*4 + 2*j]   = h;  BL[br*20 + bg*4 + 2*j]   = l;
                split2(wb[j].z, wb[j].w, h, l);
                BH[br*20 + bg*4 + 2*j+1] = h;  BL[br*20 + bg*4 + 2*j+1] = l;
            }
        }
        __syncthreads();
    }

    // ---- cross-half combine + write chunk partials
    if (tig == 0) {
#pragma unroll
        for (int mt = 0; mt < 2; mt++)
#pragma unroll
            for (int rh = 0; rh < 2; rh++) {
                const int row = wm + mt*16 + rh*8 + gid;
                smx[hf][row] = runm[mt][rh];
                ssm[hf][row] = runs[mt][rh];
            }
    }
    __syncthreads();
    if (t < 128) {
        const float m0v = smx[0][t], m1v = smx[1][t];
        const float s0 = ssm[0][t], s1 = ssm[1][t];
        const float M = fmaxf(m0v, m1v);
        float S = 0.0f;
        if (m0v != neg_inf()) S += s0 * __expf(m0v - M);
        if (m1v != neg_inf()) S += s1 * __expf(m1v - M);
        const size_t row = (size_t)bh * S_ + m0 + t;
        cmax[row * NCHUNK + blockIdx.x] = M;
        csum[row * NCHUNK + blockIdx.x] = S;
    }
}

// ======================================================================
__global__ __launch_bounds__(256)
void chunk_reduce(const float* __restrict__ cmax,
                  const float* __restrict__ csum,
                  float* __restrict__ gmax,
                  float* __restrict__ ginv)
{
    const int r = blockIdx.x * 256 + threadIdx.x;
    if (r >= BH_ * S_) return;
    float M = neg_inf(), S = 0.0f;
#pragma unroll
    for (int c = 0; c < NCHUNK; c++) {
        const float m = cmax[(size_t)r * NCHUNK + c];
        const float s = csum[(size_t)r * NCHUNK + c];
        if (m > M) { S = S * __expf(M - m) + s; M = m; }
        else if (m != neg_inf()) { S += s * __expf(m - M); }
    }
    gmax[r] = M;
    ginv[r] = 1.0f / S;
}

// ======================================================================
__global__ __launch_bounds__(256)
void vsplit_kernel(const float* __restrict__ Vp,
                   unsigned* __restrict__ Vth,
                   unsigned* __restrict__ Vtl)
{
    __shared__ float tile[32][65];
    const int t = threadIdx.x;
    const int n0 = blockIdx.x * 32;
    const int bh = blockIdx.y;

#pragma unroll
    for (int i = 0; i < 8; i++) {
        const int idx = t + i * 256;
        const int r = idx >> 6, c = idx & 63;
        tile[r][c] = Vp[((size_t)bh * S_ + n0 + r) * DEP_ + c];
    }
    __syncthreads();

#pragma unroll
    for (int i = 0; i < 4; i++) {
        const int idx = t * 4 + i;
        const int d = idx >> 4, np = idx & 15;
        unsigned h, l;
        split2(tile[2*np][d], tile[2*np + 1][d], h, l);
        const size_t o = ((size_t)bh * DEP_ + d) * (S_/2) + n0/2 + np;
        Vth[o] = h;
        Vtl[o] = l;
    }
}

// ======================================================================
// ctx v2: double-buffered A and V stages, ONE sync per 32-n slab.
// dyn smem (words): A stage st: AH @ st*5120, AL @ st*5120+2560;
//   V stage st: VH @ 10240 + st*2560, VL @ +1280. total 15360 words.
// grid (16, 24)
// ======================================================================
__global__ __launch_bounds__(256, 2)
void ctx_bf16(float* __restrict__ attn,
              const unsigned* __restrict__ Vth,
              const unsigned* __restrict__ Vtl,
              const float* __restrict__ gmax,
              const float* __restrict__ ginv,
              float* __restrict__ ctx)
{
    extern __shared__ unsigned dsm[];

    const int t = threadIdx.x, wid = t >> 5, lane = t & 31;
    const int gid = lane >> 2, tig = lane & 3;
    const int m0 = blockIdx.x * 128;
    const int bh = blockIdx.y;
    const int b  = bh / H_, h = bh % H_;
    const int wm = (wid & 3) * 32, wd = (wid >> 2) * 32;

    const int a_r = lane & 15, a_c = ((lane >> 4) & 1) * 4;
    const int b_r = (lane & 7) + ((lane >> 4) & 1) * 8;
    const int b_c = ((lane >> 3) & 1) * 4;

    const int lr = t >> 1, lg = t & 1;
    const int vr = t >> 2, vg = t & 3;

    float* Ap = attn + ((size_t)bh * S_ + m0 + lr) * S_ + lg * 16;
    const unsigned* VthB = Vth + ((size_t)bh * DEP_ + vr) * (S_/2) + vg * 4;
    const unsigned* VtlB = Vtl + ((size_t)bh * DEP_ + vr) * (S_/2) + vg * 4;

    const float mr = gmax[bh * S_ + m0 + lr];
    const float ir = ginv[bh * S_ + m0 + lr];

    float acc[2][4][4];
#pragma unroll
    for (int i = 0; i < 2; i++)
#pragma unroll
        for (int j = 0; j < 4; j++)
#pragma unroll
            for (int q = 0; q < 4; q++) acc[i][j][q] = 0.0f;

    float4 av[4];
    uint4 vh4, vl4;

    // ---- prologue: slab 0 -> stage 0
#pragma unroll
    for (int j = 0; j < 4; j++) av[j] = *(const float4*)(Ap + j * 4);
    vh4 = *(const uint4*)(VthB);
    vl4 = *(const uint4*)(VtlB);
    {
        unsigned* AH = dsm;          unsigned* AL = dsm + 2560;
        unsigned* VH = dsm + 10240;  unsigned* VL = dsm + 10240 + 1280;
#pragma unroll
        for (int j = 0; j < 4; j++) {
            float4 pv;
            pv.x = __expf(av[j].x - mr) * ir;
            pv.y = __expf(av[j].y - mr) * ir;
            pv.z = __expf(av[j].z - mr) * ir;
            pv.w = __expf(av[j].w - mr) * ir;
            *(float4*)(Ap + j * 4) = pv;
            unsigned hh, ll;
            split2(pv.x, pv.y, hh, ll);
            AH[lr*20 + lg*8 + 2*j]   = hh;  AL[lr*20 + lg*8 + 2*j]   = ll;
            split2(pv.z, pv.w, hh, ll);
            AH[lr*20 + lg*8 + 2*j+1] = hh;  AL[lr*20 + lg*8 + 2*j+1] = ll;
        }
        *(uint4*)&VH[vr*20 + vg*4] = vh4;
        *(uint4*)&VL[vr*20 + vg*4] = vl4;
    }
    __syncthreads();

#pragma unroll 1
    for (int i = 0; i < 64; i++) {
        const int st = i & 1;

        if (i + 1 < 64) {
            const int nc = (i + 1) * 32;
#pragma unroll
            for (int j = 0; j < 4; j++) av[j] = *(const float4*)(Ap + nc + j * 4);
            vh4 = *(const uint4*)(VthB + nc/2);
            vl4 = *(const uint4*)(VtlB + nc/2);
        }

        // ---- mma from stage st
#pragma unroll
        for (int step = 0; step < 2; step++) {
            const int kc = step * 8;
            unsigned ah[2][4], al[2][4], bhf[2][4], blf[2][4];
#pragma unroll
            for (int mt = 0; mt < 2; mt++) {
                ldsm_x4(ah[mt], dsm + st*5120        + (wm + mt*16 + a_r)*20 + kc + a_c);
                ldsm_x4(al[mt], dsm + st*5120 + 2560 + (wm + mt*16 + a_r)*20 + kc + a_c);
            }
#pragma unroll
            for (int np = 0; np < 2; np++) {
                ldsm_x4(bhf[np], dsm + 10240 + st*2560        + (wd + np*16 + b_r)*20 + kc + b_c);
                ldsm_x4(blf[np], dsm + 10240 + st*2560 + 1280 + (wd + np*16 + b_r)*20 + kc + b_c);
            }
#pragma unroll
            for (int dt = 0; dt < 4; dt++) {
                const unsigned bh0 = bhf[dt>>1][(dt&1)*2], bh1 = bhf[dt>>1][(dt&1)*2+1];
                const unsigned bl0 = blf[dt>>1][(dt&1)*2], bl1 = blf[dt>>1][(dt&1)*2+1];
#pragma unroll
                for (int mt = 0; mt < 2; mt++) {
                    mma16(acc[mt][dt], ah[mt][0],ah[mt][1],ah[mt][2],ah[mt][3], bh0, bh1);
                    mma16(acc[mt][dt], ah[mt][0],ah[mt][1],ah[mt][2],ah[mt][3], bl0, bl1);
                    mma16(acc[mt][dt], al[mt][0],al[mt][1],al[mt][2],al[mt][3], bh0, bh1);
                }
            }
        }

        // ---- process slab i+1 -> stage st^1
        if (i + 1 < 64) {
            const int nc = (i + 1) * 32;
            const unsigned ab = (st ^ 1) * 5120;
            unsigned* AH = dsm + ab;            unsigned* AL = dsm + ab + 2560;
            unsigned* VH = dsm + 10240 + (st^1)*2560;
            unsigned* VL = VH + 1280;
#pragma unroll
            for (int j = 0; j < 4; j++) {
                float4 pv;
                pv.x = __expf(av[j].x - mr) * ir;
                pv.y = __expf(av[j].y - mr) * ir;
                pv.z = __expf(av[j].z - mr) * ir;
                pv.w = __expf(av[j].w - mr) * ir;
                *(float4*)(Ap + nc + j * 4) = pv;
                unsigned hh, ll;
                split2(pv.x, pv.y, hh, ll);
                AH[lr*20 + lg*8 + 2*j]   = hh;  AL[lr*20 + lg*8 + 2*j]   = ll;
                split2(pv.z, pv.w, hh, ll);
                AH[lr*20 + lg*8 + 2*j+1] = hh;  AL[lr*20 + lg*8 + 2*j+1] = ll;
            }
            *(uint4*)&VH[vr*20 + vg*4] = vh4;
            *(uint4*)&VL[vr*20 + vg*4] = vl4;
        }
        __syncthreads();
    }

#pragma unroll
    for (int mt = 0; mt < 2; mt++) {
#pragma unroll
        for (int dt = 0; dt < 4; dt++) {
            const int r0 = m0 + wm + mt*16 + gid;
            const int r1 = r0 + 8;
            const int d  = wd + dt*8 + tig*2;
            float2 v0 = {acc[mt][dt][0], acc[mt][dt][1]};
            float2 v1 = {acc[mt][dt][2], acc[mt][dt][3]};
            *(float2*)(ctx + ((size_t)b * S_ + r0) * D_ + h * DEP_ + d) = v0;
            *(float2*)(ctx + ((size_t)b * S_ + r1) * D_ + h * DEP_ + d) = v1;
        }
    }
}

// ======================================================================
extern "C" void kernel_launch(void* const* d_in, const int* in_sizes, int n_in,
                              void* d_out, int out_size)
{
    const float* q    = (const float*)d_in[0];
    const float* k    = (const float*)d_in[1];
    const float* v    = (const float*)d_in[2];
    const int*   mask = (const int*)  d_in[3];
    const float* wq_w = (const float*)d_in[4];
    const float* wq_b = (const float*)d_in[5];
    const float* wk_w = (const float*)d_in[6];
    const float* wk_b = (const float*)d_in[7];
    const float* wv_w = (const float*)d_in[8];
    const float* wv_b = (const float*)d_in[9];
    const float* wo_w = (const float*)d_in[10];
    const float* wo_b = (const float*)d_in[11];
    float* out = (float*)d_out;

    float *Qp, *Kp, *Vp, *ctxp, *rmax, *rinv, *cmax, *csum, *attn_s;
    unsigned *Vth, *Vtl;
    cudaGetSymbolAddress((void**)&Qp,     g_Qp);
    cudaGetSymbolAddress((void**)&Kp,     g_Kp);
    cudaGetSymbolAddress((void**)&Vp,     g_Vp);
    cudaGetSymbolAddress((void**)&ctxp,   g_ctx);
    cudaGetSymbolAddress((void**)&rmax,   g_rowmax);
    cudaGetSymbolAddress((void**)&rinv,   g_rowinv);
    cudaGetSymbolAddress((void**)&cmax,   g_cmax);
    cudaGetSymbolAddress((void**)&csum,   g_csum);
    cudaGetSymbolAddress((void**)&Vth,    g_Vth);
    cudaGetSymbolAddress((void**)&Vtl,    g_Vtl);
    cudaGetSymbolAddress((void**)&attn_s, g_attn_scratch);

    const long long need = (long long)OUT_ELEMS + (long long)ATTN_ELEMS;
    float* attn = ((long long)out_size >= need) ? (out + OUT_ELEMS) : attn_s;

    cudaFuncSetAttribute(gemm_xwT_bf16,
                         cudaFuncAttributeMaxDynamicSharedMemorySize, DYN_SMEM_BYTES);
    cudaFuncSetAttribute(logits_bf16,
                         cudaFuncAttributeMaxDynamicSharedMemorySize, DYN_SMEM_BYTES);
    cudaFuncSetAttribute(ctx_bf16,
                         cudaFuncAttributeMaxDynamicSharedMemorySize, DYN_SMEM_BYTES);

    // Q/K/V projections (Q pre-scaled by 1/8)
    dim3 pgrid(D_/64, MROWS/128);
    gemm_xwT_bf16<<<pgrid, 256, DYN_SMEM_BYTES>>>(q, wq_w, wq_b, Qp, D_, D_, 0.125f, 1);
    gemm_xwT_bf16<<<pgrid, 256, DYN_SMEM_BYTES>>>(k, wk_w, wk_b, Kp, D_, D_, 1.0f, 1);
    gemm_xwT_bf16<<<pgrid, 256, DYN_SMEM_BYTES>>>(v, wv_w, wv_b, Vp, D_, D_, 1.0f, 1);

    // pre-split/transpose V
    vsplit_kernel<<<dim3(S_/32, BH_), 256>>>(Vp, Vth, Vtl);

    // raw masked logits + per-chunk softmax partials
    logits_bf16<<<dim3(S_/256, S_/128, BH_), 256, DYN_SMEM_BYTES>>>(
        Qp, Kp, mask, attn, cmax, csum);

    // combine partials -> row stats
    chunk_reduce<<<dim3((BH_*S_ + 255)/256), 256>>>(cmax, csum, rmax, rinv);

    // ctx = softmax @ V; normalizes attn in place
    ctx_bf16<<<dim3(S_/128, BH_), 256, DYN_SMEM_BYTES>>>(
        attn, Vth, Vtl, rmax, rinv, ctxp);

    // output projection
    gemm_xwT_bf16<<<pgrid, 256, DYN_SMEM_BYTES>>>(ctxp, wo_w, wo_b, out, D_, D_, 1.0f, 0);
}